// round 1
// baseline (speedup 1.0000x reference)
#include <cuda_runtime.h>
#include <math.h>

#define Nn    20000
#define Ee    320000
#define DIMc  256
#define Hh    8
#define EDIMc 32
#define DFFc  1024
#define ETOT  (Ee + Nn)

// ---------------- scratch (device globals; no runtime allocation) ----------
static __device__ float    g_xl [(size_t)Nn * DIMc];
static __device__ float    g_xr [(size_t)Nn * DIMc];
static __device__ float    g_ee [(size_t)ETOT * DIMc];
static __device__ float    g_loop[(size_t)Nn * EDIMc];
static __device__ float    g_cnt[Nn];
static __device__ float    g_sc [(size_t)ETOT * Hh];
static __device__ unsigned g_m  [(size_t)Nn * Hh];
static __device__ float    g_den[(size_t)Nn * Hh];
static __device__ float    g_agg[(size_t)Nn * DIMc];
static __device__ float    g_h1 [(size_t)Nn * DIMc];
static __device__ float    g_h2 [(size_t)Nn * DIMc];
static __device__ float    g_ff1[(size_t)Nn * DFFc];
static __device__ float    g_ff2[(size_t)Nn * DIMc];
static __device__ float    g_sum[DIMc];
static __device__ float    g_sumsq[DIMc];

// monotonic float<->uint encoding for atomicMax on signed floats
__device__ __forceinline__ unsigned fenc(float f) {
    unsigned u = __float_as_uint(f);
    return (u & 0x80000000u) ? ~u : (u | 0x80000000u);
}
__device__ __forceinline__ float fdec(unsigned u) {
    return (u & 0x80000000u) ? __uint_as_float(u & 0x7fffffffu)
                             : __uint_as_float(~u);
}

// ---------------- zero / init kernels ---------------------------------------
__global__ void k_zero_loop() {
    int i = blockIdx.x * blockDim.x + threadIdx.x;
    if (i < Nn * EDIMc) g_loop[i] = 0.f;
    if (i < Nn)         g_cnt[i]  = 0.f;
}
__global__ void k_zero_gat() {
    int i = blockIdx.x * blockDim.x + threadIdx.x;
    if (i >= Nn * DIMc) return;
    g_agg[i] = 0.f;
    if (i < Nn * Hh) { g_m[i] = 0u; g_den[i] = 0.f; }
}
__global__ void k_zero_stats() {
    int t = threadIdx.x;
    if (t < DIMc) { g_sum[t] = 0.f; g_sumsq[t] = 0.f; }
}

// ---------------- self-loop edge-feature mean -------------------------------
__global__ void k_loop_accum(const int* __restrict__ dst, const float* __restrict__ ew) {
    int w    = (blockIdx.x * blockDim.x + threadIdx.x) >> 5;
    int lane = threadIdx.x & 31;
    if (w >= Ee) return;
    int d = dst[w];
    atomicAdd(&g_loop[d * EDIMc + lane], ew[(size_t)w * EDIMc + lane]);
    if (lane == 0) atomicAdd(&g_cnt[d], 1.f);
}
__global__ void k_loop_div() {
    int i = blockIdx.x * blockDim.x + threadIdx.x;
    if (i >= Nn * EDIMc) return;
    g_loop[i] /= fmaxf(g_cnt[i >> 5], 1.f);
}

// ---------------- SGEMM: C[M,Nc] = A[M,K] @ B[K,Nc] (+bias, +relu) ----------
// BM=BN=64, BK=16, 256 threads, 4x4 per thread. K % 16 == 0, Nc % 64 == 0.
template<bool RELU, bool BIAS>
__global__ void sgemm64(const float* __restrict__ A, const float* __restrict__ B,
                        const float* __restrict__ bias, float* __restrict__ C,
                        int M, int K, int Nc) {
    __shared__ float As[16][64];
    __shared__ float Bs[16][64];
    int tid = threadIdx.x;
    int tx = tid & 15, ty = tid >> 4;
    int row0 = blockIdx.y * 64, col0 = blockIdx.x * 64;

    int arow = tid >> 2;          // 0..63
    int acol = (tid & 3) << 2;    // 0,4,8,12
    int brow = tid >> 4;          // 0..15
    int bcol = (tid & 15) << 2;   // 0..60

    float acc[4][4];
#pragma unroll
    for (int i = 0; i < 4; i++)
#pragma unroll
        for (int j = 0; j < 4; j++) acc[i][j] = 0.f;

    for (int k0 = 0; k0 < K; k0 += 16) {
        float4 av = make_float4(0.f, 0.f, 0.f, 0.f);
        int ar = row0 + arow;
        if (ar < M) av = *(const float4*)&A[(size_t)ar * K + k0 + acol];
        As[acol + 0][arow] = av.x;
        As[acol + 1][arow] = av.y;
        As[acol + 2][arow] = av.z;
        As[acol + 3][arow] = av.w;
        float4 bv = *(const float4*)&B[(size_t)(k0 + brow) * Nc + col0 + bcol];
        *(float4*)&Bs[brow][bcol] = bv;
        __syncthreads();
#pragma unroll
        for (int k = 0; k < 16; k++) {
            float4 a4 = *(const float4*)&As[k][ty << 2];
            float4 b4 = *(const float4*)&Bs[k][tx << 2];
            float aa[4] = {a4.x, a4.y, a4.z, a4.w};
            float bb[4] = {b4.x, b4.y, b4.z, b4.w};
#pragma unroll
            for (int i = 0; i < 4; i++)
#pragma unroll
                for (int j = 0; j < 4; j++) acc[i][j] += aa[i] * bb[j];
        }
        __syncthreads();
    }
#pragma unroll
    for (int i = 0; i < 4; i++) {
        int r = row0 + (ty << 2) + i;
        if (r >= M) continue;
#pragma unroll
        for (int j = 0; j < 4; j++) {
            int c = col0 + (tx << 2) + j;
            float v = acc[i][j];
            if (BIAS) v += bias[c];
            if (RELU) v = fmaxf(v, 0.f);
            C[(size_t)r * Nc + c] = v;
        }
    }
}

// ---------------- GATv2 edge score: one warp per edge -----------------------
__global__ void k_score(const int* __restrict__ src, const int* __restrict__ dst,
                        const float* __restrict__ att) {
    __shared__ float att_s[DIMc];
    if (threadIdx.x < DIMc) att_s[threadIdx.x] = att[threadIdx.x];
    __syncthreads();
    int e    = blockIdx.x * (blockDim.x >> 5) + (threadIdx.x >> 5);
    int lane = threadIdx.x & 31;
    if (e >= ETOT) return;
    int s, d;
    if (e < Ee) { s = src[e]; d = dst[e]; } else { s = e - Ee; d = s; }
    const float* xlp = g_xl + (size_t)s * DIMc;
    const float* xrp = g_xr + (size_t)d * DIMc;
    const float* eep = g_ee + (size_t)e * DIMc;
#pragma unroll
    for (int h = 0; h < Hh; h++) {
        int col = (h << 5) + lane;
        float z = xlp[col] + xrp[col] + eep[col];
        z = (z > 0.f) ? z : 0.2f * z;
        float p = z * att_s[col];
#pragma unroll
        for (int off = 16; off; off >>= 1) p += __shfl_xor_sync(0xffffffffu, p, off);
        if (lane == 0) {
            g_sc[(size_t)e * Hh + h] = p;
            atomicMax(&g_m[d * Hh + h], fenc(p));
        }
    }
}

// ---------------- exp + denominator -----------------------------------------
__global__ void k_expden(const int* __restrict__ dst) {
    int i = blockIdx.x * blockDim.x + threadIdx.x;
    if (i >= ETOT * Hh) return;
    int e = i >> 3, h = i & 7;
    int d = (e < Ee) ? dst[e] : (e - Ee);
    float ex = __expf(g_sc[i] - fdec(g_m[d * Hh + h]));
    g_sc[i] = ex;
    atomicAdd(&g_den[d * Hh + h], ex);
}

// ---------------- weighted aggregation: one warp per edge -------------------
__global__ void k_agg(const int* __restrict__ src, const int* __restrict__ dst) {
    int e    = blockIdx.x * (blockDim.x >> 5) + (threadIdx.x >> 5);
    int lane = threadIdx.x & 31;
    if (e >= ETOT) return;
    int s, d;
    if (e < Ee) { s = src[e]; d = dst[e]; } else { s = e - Ee; d = s; }
    const float* xlp = g_xl + (size_t)s * DIMc;
    float* outp = g_agg + (size_t)d * DIMc;
#pragma unroll
    for (int h = 0; h < Hh; h++) {
        float alpha = g_sc[(size_t)e * Hh + h] / g_den[d * Hh + h];
        int col = (h << 5) + lane;
        atomicAdd(&outp[col], alpha * xlp[col]);
    }
}

// ---------------- BatchNorm (training-mode batch stats) ---------------------
__global__ void k_bnstats(const float* __restrict__ X) {
    int c = threadIdx.x;           // 256 threads = 256 columns
    float s = 0.f, q = 0.f;
    for (int r = blockIdx.x; r < Nn; r += gridDim.x) {
        float v = X[(size_t)r * DIMc + c];
        s += v; q += v * v;
    }
    atomicAdd(&g_sum[c], s);
    atomicAdd(&g_sumsq[c], q);
}
__global__ void k_bnapply(const float* __restrict__ X, const float* __restrict__ gam,
                          const float* __restrict__ bet, const float* __restrict__ res,
                          float* __restrict__ out) {
    int i = blockIdx.x * blockDim.x + threadIdx.x;
    if (i >= Nn * DIMc) return;
    int c = i & (DIMc - 1);
    float mu  = g_sum[c]   * (1.f / Nn);
    float var = g_sumsq[c] * (1.f / Nn) - mu * mu;
    float y = (X[i] - mu) * rsqrtf(var + 1e-5f) * gam[c] + bet[c];
    y = (y > 0.f) ? y : 0.01f * y;
    out[i] = res[i] + y;
}

// ---------------- host orchestration ----------------------------------------
static inline int cdiv(int a, int b) { return (a + b - 1) / b; }

static void run_gat(const float* x, const float* Wl, const float* Wr, const float* We,
                    const float* att, const int* src, const int* dst, const float* ew,
                    float* xl, float* xr, float* ee, float* loop) {
    k_zero_gat<<<cdiv(Nn * DIMc, 256), 256>>>();
    dim3 gx(DIMc / 64, cdiv(Nn, 64));
    sgemm64<false, false><<<gx, 256>>>(x, Wl, nullptr, xl, Nn, DIMc, DIMc);
    sgemm64<false, false><<<gx, 256>>>(x, Wr, nullptr, xr, Nn, DIMc, DIMc);
    dim3 ge(DIMc / 64, cdiv(Ee, 64));
    sgemm64<false, false><<<ge, 256>>>(ew, We, nullptr, ee, Ee, EDIMc, DIMc);
    dim3 gl(DIMc / 64, cdiv(Nn, 64));
    sgemm64<false, false><<<gl, 256>>>(loop, We, nullptr, ee + (size_t)Ee * DIMc,
                                       Nn, EDIMc, DIMc);
    int nb = cdiv(ETOT, 8);            // 8 warps / block, 1 warp / edge
    k_score<<<nb, 256>>>(src, dst, att);
    k_expden<<<cdiv(ETOT * Hh, 256), 256>>>(dst);
    k_agg<<<nb, 256>>>(src, dst);
}

extern "C" void kernel_launch(void* const* d_in, const int* in_sizes, int n_in,
                              void* d_out, int out_size) {
    const float* nf    = (const float*)d_in[0];
    const int*   ei    = (const int*)  d_in[1];
    const float* ew    = (const float*)d_in[2];
    const float* g1_Wl = (const float*)d_in[3];
    const float* g1_Wr = (const float*)d_in[4];
    const float* g1_We = (const float*)d_in[5];
    const float* g1_at = (const float*)d_in[6];
    // d_in[7] = g1_b : cancels inside BatchNorm (mean-subtracted)
    const float* g2_Wl = (const float*)d_in[8];
    const float* g2_Wr = (const float*)d_in[9];
    const float* g2_We = (const float*)d_in[10];
    const float* g2_at = (const float*)d_in[11];
    // d_in[12] = g2_b : cancels
    const float* n1_g  = (const float*)d_in[13];
    const float* n1_b  = (const float*)d_in[14];
    const float* n2_g  = (const float*)d_in[15];
    const float* n2_b  = (const float*)d_in[16];
    const float* n3_g  = (const float*)d_in[17];
    const float* n3_b  = (const float*)d_in[18];
    const float* ff_W1 = (const float*)d_in[19];
    const float* ff_b1 = (const float*)d_in[20];
    const float* ff_W2 = (const float*)d_in[21];
    // d_in[22] = ff_b2 : cancels inside BatchNorm
    const int* src = ei;
    const int* dst = ei + Ee;
    float* out = (float*)d_out;

    void *p;
    cudaGetSymbolAddress(&p, g_xl);   float* xl   = (float*)p;
    cudaGetSymbolAddress(&p, g_xr);   float* xr   = (float*)p;
    cudaGetSymbolAddress(&p, g_ee);   float* ee   = (float*)p;
    cudaGetSymbolAddress(&p, g_loop); float* loop = (float*)p;
    cudaGetSymbolAddress(&p, g_agg);  float* agg  = (float*)p;
    cudaGetSymbolAddress(&p, g_h1);   float* h1   = (float*)p;
    cudaGetSymbolAddress(&p, g_h2);   float* h2   = (float*)p;
    cudaGetSymbolAddress(&p, g_ff1);  float* ff1  = (float*)p;
    cudaGetSymbolAddress(&p, g_ff2);  float* ff2  = (float*)p;

    // self-loop edge features (shared by both GAT layers)
    k_zero_loop<<<cdiv(Nn * EDIMc, 256), 256>>>();
    k_loop_accum<<<cdiv(Ee * 32, 256), 256>>>(dst, ew);
    k_loop_div<<<cdiv(Nn * EDIMc, 256), 256>>>();

    // ---- block 1 ----
    run_gat(nf, g1_Wl, g1_Wr, g1_We, g1_at, src, dst, ew, xl, xr, ee, loop);
    k_zero_stats<<<1, 256>>>();
    k_bnstats<<<256, 256>>>(agg);
    k_bnapply<<<cdiv(Nn * DIMc, 256), 256>>>(agg, n1_g, n1_b, nf, h1);

    // ---- block 2 ----
    run_gat(h1, g2_Wl, g2_Wr, g2_We, g2_at, src, dst, ew, xl, xr, ee, loop);
    k_zero_stats<<<1, 256>>>();
    k_bnstats<<<256, 256>>>(agg);
    k_bnapply<<<cdiv(Nn * DIMc, 256), 256>>>(agg, n2_g, n2_b, h1, h2);

    // ---- feed-forward ----
    dim3 gf1(DFFc / 64, cdiv(Nn, 64));
    sgemm64<true, true><<<gf1, 256>>>(h2, ff_W1, ff_b1, ff1, Nn, DIMc, DFFc);
    dim3 gf2(DIMc / 64, cdiv(Nn, 64));
    sgemm64<false, false><<<gf2, 256>>>(ff1, ff_W2, nullptr, ff2, Nn, DFFc, DIMc);
    k_zero_stats<<<1, 256>>>();
    k_bnstats<<<256, 256>>>(ff2);
    k_bnapply<<<cdiv(Nn * DIMc, 256), 256>>>(ff2, n3_g, n3_b, h2, out);
}

// round 3
// speedup vs baseline: 1.2586x; 1.2586x over previous
#include <cuda_runtime.h>
#include <cuda_bf16.h>
#include <math.h>
#include <stdint.h>

#define Nn    20000
#define Ee    320000
#define DIMc  256
#define Hh    8
#define EDIMc 32
#define DFFc  1024
#define ETOT  (Ee + Nn)

// ---------------- scratch (device globals; no runtime allocation) ----------
static __device__ float    g_xl [(size_t)Nn * DIMc];
static __device__ float    g_xr [(size_t)Nn * DIMc];
static __device__ float    g_ee [(size_t)ETOT * DIMc];
static __device__ float    g_loop[(size_t)Nn * EDIMc];
static __device__ float    g_cnt[Nn];
static __device__ float    g_sc [(size_t)ETOT * Hh];
static __device__ unsigned g_m  [(size_t)Nn * Hh];
static __device__ float    g_den[(size_t)Nn * Hh];
static __device__ float    g_agg[(size_t)Nn * DIMc];
static __device__ float    g_h1 [(size_t)Nn * DIMc];
static __device__ float    g_h2 [(size_t)Nn * DIMc];
static __device__ float    g_ff1[(size_t)Nn * DFFc];
static __device__ float    g_ff2[(size_t)Nn * DIMc];
static __device__ float    g_sum[DIMc];
static __device__ float    g_sumsq[DIMc];

// bf16 hi/lo split buffers
static __device__ __nv_bfloat16 g_Ahi[(size_t)Nn * DFFc];
static __device__ __nv_bfloat16 g_Alo[(size_t)Nn * DFFc];
static __device__ __nv_bfloat16 g_EAhi[(size_t)ETOT * EDIMc];
static __device__ __nv_bfloat16 g_EAlo[(size_t)ETOT * EDIMc];
#define WT_TOTAL (65536*4 + 8192*2 + 262144*2)
static __device__ __nv_bfloat16 g_WThi[WT_TOTAL];
static __device__ __nv_bfloat16 g_WTlo[WT_TOTAL];
#define OFF_WL1 0
#define OFF_WR1 65536
#define OFF_WE1 131072
#define OFF_WL2 139264
#define OFF_WR2 204800
#define OFF_WE2 270336
#define OFF_W1  278528
#define OFF_W2  540672

// ---------------- PTX helpers ------------------------------------------------
__device__ __forceinline__ uint32_t smem_u32(const void* p) {
    uint32_t a;
    asm("{ .reg .u64 t; cvta.to.shared.u64 t, %1; cvt.u32.u64 %0, t; }"
        : "=r"(a) : "l"(p));
    return a;
}
#define LDSM_X4(r0, r1, r2, r3, addr) \
    asm volatile("ldmatrix.sync.aligned.m8n8.x4.shared.b16 {%0,%1,%2,%3}, [%4];" \
                 : "=r"(r0), "=r"(r1), "=r"(r2), "=r"(r3) : "r"(addr))
#define LDSM_X2(r0, r1, addr) \
    asm volatile("ldmatrix.sync.aligned.m8n8.x2.shared.b16 {%0,%1}, [%2];" \
                 : "=r"(r0), "=r"(r1) : "r"(addr))
#define MMA16816(c, a0, a1, a2, a3, b0, b1) \
    asm volatile("mma.sync.aligned.m16n8k16.row.col.f32.bf16.bf16.f32 " \
                 "{%0,%1,%2,%3}, {%4,%5,%6,%7}, {%8,%9}, {%0,%1,%2,%3};" \
                 : "+f"((c)[0]), "+f"((c)[1]), "+f"((c)[2]), "+f"((c)[3]) \
                 : "r"(a0), "r"(a1), "r"(a2), "r"(a3), "r"(b0), "r"(b1))

// ---------------- split kernels ----------------------------------------------
__global__ void k_split(const float* __restrict__ X, __nv_bfloat16* __restrict__ hi,
                        __nv_bfloat16* __restrict__ lo, int n) {
    int i = blockIdx.x * blockDim.x + threadIdx.x;
    if (i >= n) return;
    float v = X[i];
    __nv_bfloat16 h = __float2bfloat16(v);
    hi[i] = h;
    lo[i] = __float2bfloat16(v - __bfloat162float(h));
}
// W[K,N] row-major -> WT_hi/lo[N,K]
__global__ void k_splitT(const float* __restrict__ W, __nv_bfloat16* __restrict__ hiT,
                         __nv_bfloat16* __restrict__ loT, int K, int N) {
    int i = blockIdx.x * blockDim.x + threadIdx.x;
    if (i >= K * N) return;
    int k = i / N, n = i - k * N;
    float v = W[i];
    __nv_bfloat16 h = __float2bfloat16(v);
    hiT[(size_t)n * K + k] = h;
    loT[(size_t)n * K + k] = __float2bfloat16(v - __bfloat162float(h));
}
__global__ void k_split_ea(const float* __restrict__ ew) {
    int i = blockIdx.x * blockDim.x + threadIdx.x;
    if (i >= ETOT * EDIMc) return;
    float v = (i < Ee * EDIMc) ? ew[i] : g_loop[i - Ee * EDIMc];
    __nv_bfloat16 h = __float2bfloat16(v);
    g_EAhi[i] = h;
    g_EAlo[i] = __float2bfloat16(v - __bfloat162float(h));
}

// ---------------- bf16x3 mma.sync GEMM ---------------------------------------
// C[M,Nc] = A@B.  A = Ahi+Alo [M,K] row-major bf16.  B given as BT = Bhi/Blo
// [Nc,K] row-major bf16 (i.e. B col-major). 3 products: AhBh + AlBh + AhBl,
// fp32 accumulate.
#define SA 72                      // smem row stride in elements (9 x 16B units)
#define TILE_ELEMS (128 * SA)
#define GEMM_SMEM (4 * TILE_ELEMS * 2)

__device__ __forceinline__ void ld_tile(const __nv_bfloat16* __restrict__ G,
                                        int r0, int rlim, int K, int k0,
                                        __nv_bfloat16* __restrict__ s, int tid) {
#pragma unroll
    for (int q = tid; q < 1024; q += 256) {   // 128 rows x 8 x uint4
        int row = q >> 3, u = q & 7;
        uint4 v = make_uint4(0u, 0u, 0u, 0u);
        int gr = r0 + row, gk = k0 + (u << 3);
        if (gr < rlim && gk < K) v = *(const uint4*)(G + (size_t)gr * K + gk);
        *(uint4*)(s + row * SA + (u << 3)) = v;
    }
}

template<bool RELU, bool BIAS>
__global__ void __launch_bounds__(256, 2) gemm_mma(
    const __nv_bfloat16* __restrict__ Ah, const __nv_bfloat16* __restrict__ Al,
    const __nv_bfloat16* __restrict__ Bh, const __nv_bfloat16* __restrict__ Bl,
    const float* __restrict__ bias, float* __restrict__ C,
    int M, int K, int Nc) {
    extern __shared__ __nv_bfloat16 sm[];
    __nv_bfloat16* sAh = sm;
    __nv_bfloat16* sAl = sm + TILE_ELEMS;
    __nv_bfloat16* sBh = sm + 2 * TILE_ELEMS;
    __nv_bfloat16* sBl = sm + 3 * TILE_ELEMS;

    int tid  = threadIdx.x;
    int lane = tid & 31;
    int w    = tid >> 5;
    int wr   = w & 1;          // 64-row block
    int wc   = w >> 1;         // 32-col block
    int row0 = blockIdx.y * 128;
    int col0 = blockIdx.x * 128;

    float acc[4][4][4];
#pragma unroll
    for (int i = 0; i < 4; i++)
#pragma unroll
        for (int j = 0; j < 4; j++)
#pragma unroll
            for (int q = 0; q < 4; q++) acc[i][j][q] = 0.f;

    uint32_t bAh = smem_u32(sAh), bAl = smem_u32(sAl);
    uint32_t bBh = smem_u32(sBh), bBl = smem_u32(sBl);

    // per-lane fragment offsets (bytes)
    uint32_t aoff = (uint32_t)(((wr * 64 + (lane & 15)) * SA + (lane >> 4) * 8) * 2);
    uint32_t boff = (uint32_t)(((wc * 32 + (lane & 7)) * SA + ((lane >> 3) & 1) * 8) * 2);

    for (int k0 = 0; k0 < K; k0 += 64) {
        ld_tile(Ah, row0, M, K, k0, sAh, tid);
        ld_tile(Al, row0, M, K, k0, sAl, tid);
        ld_tile(Bh, col0, Nc, K, k0, sBh, tid);
        ld_tile(Bl, col0, Nc, K, k0, sBl, tid);
        __syncthreads();

#pragma unroll
        for (int ks = 0; ks < 4; ks++) {
            uint32_t kb = (uint32_t)(ks * 16 * 2);   // byte offset along k
#pragma unroll
            for (int pass = 0; pass < 3; pass++) {
                uint32_t ab = (pass == 1 ? bAl : bAh) + aoff + kb;
                uint32_t bb = (pass == 2 ? bBl : bBh) + boff + kb;
                uint32_t a[4][4];
#pragma unroll
                for (int mi = 0; mi < 4; mi++)
                    LDSM_X4(a[mi][0], a[mi][1], a[mi][2], a[mi][3],
                            ab + (uint32_t)(mi * 16 * SA * 2));
                uint32_t b[4][2];
#pragma unroll
                for (int ni = 0; ni < 4; ni++)
                    LDSM_X2(b[ni][0], b[ni][1], bb + (uint32_t)(ni * 8 * SA * 2));
#pragma unroll
                for (int mi = 0; mi < 4; mi++)
#pragma unroll
                    for (int ni = 0; ni < 4; ni++)
                        MMA16816(acc[mi][ni], a[mi][0], a[mi][1], a[mi][2], a[mi][3],
                                 b[ni][0], b[ni][1]);
            }
        }
        __syncthreads();
    }

    // epilogue
#pragma unroll
    for (int mi = 0; mi < 4; mi++) {
#pragma unroll
        for (int ni = 0; ni < 4; ni++) {
            int r = row0 + wr * 64 + mi * 16 + (lane >> 2);
            int c = col0 + wc * 32 + ni * 8 + (lane & 3) * 2;
            float v0 = acc[mi][ni][0], v1 = acc[mi][ni][1];
            float v2 = acc[mi][ni][2], v3 = acc[mi][ni][3];
            if (BIAS) {
                float b0 = bias[c], b1 = bias[c + 1];
                v0 += b0; v1 += b1; v2 += b0; v3 += b1;
            }
            if (RELU) {
                v0 = fmaxf(v0, 0.f); v1 = fmaxf(v1, 0.f);
                v2 = fmaxf(v2, 0.f); v3 = fmaxf(v3, 0.f);
            }
            if (r < M)     { C[(size_t)r * Nc + c] = v0;       C[(size_t)r * Nc + c + 1] = v1; }
            if (r + 8 < M) { C[(size_t)(r + 8) * Nc + c] = v2; C[(size_t)(r + 8) * Nc + c + 1] = v3; }
        }
    }
}

// ---------------- misc kernels (round-1, known-correct) ----------------------
__device__ __forceinline__ unsigned fenc(float f) {
    unsigned u = __float_as_uint(f);
    return (u & 0x80000000u) ? ~u : (u | 0x80000000u);
}
__device__ __forceinline__ float fdec(unsigned u) {
    return (u & 0x80000000u) ? __uint_as_float(u & 0x7fffffffu) : __uint_as_float(~u);
}
__global__ void k_zero_loop() {
    int i = blockIdx.x * blockDim.x + threadIdx.x;
    if (i < Nn * EDIMc) g_loop[i] = 0.f;
    if (i < Nn)         g_cnt[i]  = 0.f;
}
__global__ void k_zero_gat() {
    int i = blockIdx.x * blockDim.x + threadIdx.x;
    if (i >= Nn * DIMc) return;
    g_agg[i] = 0.f;
    if (i < Nn * Hh) { g_m[i] = 0u; g_den[i] = 0.f; }
}
__global__ void k_zero_stats() {
    int t = threadIdx.x;
    if (t < DIMc) { g_sum[t] = 0.f; g_sumsq[t] = 0.f; }
}
__global__ void k_loop_accum(const int* __restrict__ dst, const float* __restrict__ ew) {
    int w    = (blockIdx.x * blockDim.x + threadIdx.x) >> 5;
    int lane = threadIdx.x & 31;
    if (w >= Ee) return;
    int d = dst[w];
    atomicAdd(&g_loop[d * EDIMc + lane], ew[(size_t)w * EDIMc + lane]);
    if (lane == 0) atomicAdd(&g_cnt[d], 1.f);
}
__global__ void k_loop_div() {
    int i = blockIdx.x * blockDim.x + threadIdx.x;
    if (i >= Nn * EDIMc) return;
    g_loop[i] /= fmaxf(g_cnt[i >> 5], 1.f);
}
__global__ void k_score(const int* __restrict__ src, const int* __restrict__ dst,
                        const float* __restrict__ att) {
    __shared__ float att_s[DIMc];
    if (threadIdx.x < DIMc) att_s[threadIdx.x] = att[threadIdx.x];
    __syncthreads();
    int e    = blockIdx.x * (blockDim.x >> 5) + (threadIdx.x >> 5);
    int lane = threadIdx.x & 31;
    if (e >= ETOT) return;
    int s, d;
    if (e < Ee) { s = src[e]; d = dst[e]; } else { s = e - Ee; d = s; }
    const float* xlp = g_xl + (size_t)s * DIMc;
    const float* xrp = g_xr + (size_t)d * DIMc;
    const float* eep = g_ee + (size_t)e * DIMc;
#pragma unroll
    for (int h = 0; h < Hh; h++) {
        int col = (h << 5) + lane;
        float z = xlp[col] + xrp[col] + eep[col];
        z = (z > 0.f) ? z : 0.2f * z;
        float p = z * att_s[col];
#pragma unroll
        for (int off = 16; off; off >>= 1) p += __shfl_xor_sync(0xffffffffu, p, off);
        if (lane == 0) {
            g_sc[(size_t)e * Hh + h] = p;
            atomicMax(&g_m[d * Hh + h], fenc(p));
        }
    }
}
__global__ void k_expden(const int* __restrict__ dst) {
    int i = blockIdx.x * blockDim.x + threadIdx.x;
    if (i >= ETOT * Hh) return;
    int e = i >> 3, h = i & 7;
    int d = (e < Ee) ? dst[e] : (e - Ee);
    float ex = __expf(g_sc[i] - fdec(g_m[d * Hh + h]));
    g_sc[i] = ex;
    atomicAdd(&g_den[d * Hh + h], ex);
}
__global__ void k_agg(const int* __restrict__ src, const int* __restrict__ dst) {
    int e    = blockIdx.x * (blockDim.x >> 5) + (threadIdx.x >> 5);
    int lane = threadIdx.x & 31;
    if (e >= ETOT) return;
    int s, d;
    if (e < Ee) { s = src[e]; d = dst[e]; } else { s = e - Ee; d = s; }
    const float* xlp = g_xl + (size_t)s * DIMc;
    float* outp = g_agg + (size_t)d * DIMc;
#pragma unroll
    for (int h = 0; h < Hh; h++) {
        float alpha = g_sc[(size_t)e * Hh + h] / g_den[d * Hh + h];
        int col = (h << 5) + lane;
        atomicAdd(&outp[col], alpha * xlp[col]);
    }
}
__global__ void k_bnstats(const float* __restrict__ X) {
    int c = threadIdx.x;
    float s = 0.f, q = 0.f;
    for (int r = blockIdx.x; r < Nn; r += gridDim.x) {
        float v = X[(size_t)r * DIMc + c];
        s += v; q += v * v;
    }
    atomicAdd(&g_sum[c], s);
    atomicAdd(&g_sumsq[c], q);
}
__global__ void k_bnapply(const float* __restrict__ X, const float* __restrict__ gam,
                          const float* __restrict__ bet, const float* __restrict__ res,
                          float* __restrict__ out) {
    int i = blockIdx.x * blockDim.x + threadIdx.x;
    if (i >= Nn * DIMc) return;
    int c = i & (DIMc - 1);
    float mu  = g_sum[c]   * (1.f / Nn);
    float var = g_sumsq[c] * (1.f / Nn) - mu * mu;
    float y = (X[i] - mu) * rsqrtf(var + 1e-5f) * gam[c] + bet[c];
    y = (y > 0.f) ? y : 0.01f * y;
    out[i] = res[i] + y;
}

// ---------------- host orchestration -----------------------------------------
static inline int cdiv(int a, int b) { return (a + b - 1) / b; }

extern "C" void kernel_launch(void* const* d_in, const int* in_sizes, int n_in,
                              void* d_out, int out_size) {
    const float* nf    = (const float*)d_in[0];
    const int*   ei    = (const int*)  d_in[1];
    const float* ew    = (const float*)d_in[2];
    const float* g1_Wl = (const float*)d_in[3];
    const float* g1_Wr = (const float*)d_in[4];
    const float* g1_We = (const float*)d_in[5];
    const float* g1_at = (const float*)d_in[6];
    const float* g2_Wl = (const float*)d_in[8];
    const float* g2_Wr = (const float*)d_in[9];
    const float* g2_We = (const float*)d_in[10];
    const float* g2_at = (const float*)d_in[11];
    const float* n1_g  = (const float*)d_in[13];
    const float* n1_b  = (const float*)d_in[14];
    const float* n2_g  = (const float*)d_in[15];
    const float* n2_b  = (const float*)d_in[16];
    const float* n3_g  = (const float*)d_in[17];
    const float* n3_b  = (const float*)d_in[18];
    const float* ff_W1 = (const float*)d_in[19];
    const float* ff_b1 = (const float*)d_in[20];
    const float* ff_W2 = (const float*)d_in[21];
    const int* src = ei;
    const int* dst = ei + Ee;
    float* out = (float*)d_out;

    void* p;
    cudaGetSymbolAddress(&p, g_xl);   float* xl   = (float*)p;
    cudaGetSymbolAddress(&p, g_xr);   float* xr   = (float*)p;
    cudaGetSymbolAddress(&p, g_ee);   float* ee   = (float*)p;
    cudaGetSymbolAddress(&p, g_agg);  float* agg  = (float*)p;
    cudaGetSymbolAddress(&p, g_h1);   float* h1   = (float*)p;
    cudaGetSymbolAddress(&p, g_h2);   float* h2   = (float*)p;
    cudaGetSymbolAddress(&p, g_ff1);  float* ff1  = (float*)p;
    cudaGetSymbolAddress(&p, g_ff2);  float* ff2  = (float*)p;
    cudaGetSymbolAddress(&p, g_Ahi);  __nv_bfloat16* Ahi = (__nv_bfloat16*)p;
    cudaGetSymbolAddress(&p, g_Alo);  __nv_bfloat16* Alo = (__nv_bfloat16*)p;
    cudaGetSymbolAddress(&p, g_EAhi); __nv_bfloat16* EAhi = (__nv_bfloat16*)p;
    cudaGetSymbolAddress(&p, g_EAlo); __nv_bfloat16* EAlo = (__nv_bfloat16*)p;
    cudaGetSymbolAddress(&p, g_WThi); __nv_bfloat16* WTh = (__nv_bfloat16*)p;
    cudaGetSymbolAddress(&p, g_WTlo); __nv_bfloat16* WTl = (__nv_bfloat16*)p;

    cudaFuncSetAttribute(gemm_mma<false, false>,
                         cudaFuncAttributeMaxDynamicSharedMemorySize, GEMM_SMEM);
    cudaFuncSetAttribute(gemm_mma<true, true>,
                         cudaFuncAttributeMaxDynamicSharedMemorySize, GEMM_SMEM);

    // ---- weight splits/transposes ----
    k_splitT<<<cdiv(DIMc * DIMc, 256), 256>>>(g1_Wl, WTh + OFF_WL1, WTl + OFF_WL1, DIMc, DIMc);
    k_splitT<<<cdiv(DIMc * DIMc, 256), 256>>>(g1_Wr, WTh + OFF_WR1, WTl + OFF_WR1, DIMc, DIMc);
    k_splitT<<<cdiv(EDIMc * DIMc, 256), 256>>>(g1_We, WTh + OFF_WE1, WTl + OFF_WE1, EDIMc, DIMc);
    k_splitT<<<cdiv(DIMc * DIMc, 256), 256>>>(g2_Wl, WTh + OFF_WL2, WTl + OFF_WL2, DIMc, DIMc);
    k_splitT<<<cdiv(DIMc * DIMc, 256), 256>>>(g2_Wr, WTh + OFF_WR2, WTl + OFF_WR2, DIMc, DIMc);
    k_splitT<<<cdiv(EDIMc * DIMc, 256), 256>>>(g2_We, WTh + OFF_WE2, WTl + OFF_WE2, EDIMc, DIMc);
    k_splitT<<<cdiv(DIMc * DFFc, 256), 256>>>(ff_W1, WTh + OFF_W1, WTl + OFF_W1, DIMc, DFFc);
    k_splitT<<<cdiv(DFFc * DIMc, 256), 256>>>(ff_W2, WTh + OFF_W2, WTl + OFF_W2, DFFc, DIMc);

    // ---- self-loop edge features + edge-attr split ----
    k_zero_loop<<<cdiv(Nn * EDIMc, 256), 256>>>();
    k_loop_accum<<<cdiv(Ee * 32, 256), 256>>>(dst, ew);
    k_loop_div<<<cdiv(Nn * EDIMc, 256), 256>>>();
    k_split_ea<<<cdiv(ETOT * EDIMc, 256), 256>>>(ew);

    dim3 gNode(DIMc / 128, cdiv(Nn, 128));
    dim3 gEdge(DIMc / 128, cdiv(ETOT, 128));
    int nbEdge = cdiv(ETOT, 8);

    // ---- block 1 ----
    k_zero_gat<<<cdiv(Nn * DIMc, 256), 256>>>();
    k_split<<<cdiv(Nn * DIMc, 256), 256>>>(nf, Ahi, Alo, Nn * DIMc);
    gemm_mma<false, false><<<gNode, 256, GEMM_SMEM>>>(Ahi, Alo, WTh + OFF_WL1, WTl + OFF_WL1,
                                                      nullptr, xl, Nn, DIMc, DIMc);
    gemm_mma<false, false><<<gNode, 256, GEMM_SMEM>>>(Ahi, Alo, WTh + OFF_WR1, WTl + OFF_WR1,
                                                      nullptr, xr, Nn, DIMc, DIMc);
    gemm_mma<false, false><<<gEdge, 256, GEMM_SMEM>>>(EAhi, EAlo, WTh + OFF_WE1, WTl + OFF_WE1,
                                                      nullptr, ee, ETOT, EDIMc, DIMc);
    k_score<<<nbEdge, 256>>>(src, dst, g1_at);
    k_expden<<<cdiv(ETOT * Hh, 256), 256>>>(dst);
    k_agg<<<nbEdge, 256>>>(src, dst);
    k_zero_stats<<<1, 256>>>();
    k_bnstats<<<256, 256>>>(agg);
    k_bnapply<<<cdiv(Nn * DIMc, 256), 256>>>(agg, n1_g, n1_b, nf, h1);

    // ---- block 2 ----
    k_zero_gat<<<cdiv(Nn * DIMc, 256), 256>>>();
    k_split<<<cdiv(Nn * DIMc, 256), 256>>>(h1, Ahi, Alo, Nn * DIMc);
    gemm_mma<false, false><<<gNode, 256, GEMM_SMEM>>>(Ahi, Alo, WTh + OFF_WL2, WTl + OFF_WL2,
                                                      nullptr, xl, Nn, DIMc, DIMc);
    gemm_mma<false, false><<<gNode, 256, GEMM_SMEM>>>(Ahi, Alo, WTh + OFF_WR2, WTl + OFF_WR2,
                                                      nullptr, xr, Nn, DIMc, DIMc);
    gemm_mma<false, false><<<gEdge, 256, GEMM_SMEM>>>(EAhi, EAlo, WTh + OFF_WE2, WTl + OFF_WE2,
                                                      nullptr, ee, ETOT, EDIMc, DIMc);
    k_score<<<nbEdge, 256>>>(src, dst, g2_at);
    k_expden<<<cdiv(ETOT * Hh, 256), 256>>>(dst);
    k_agg<<<nbEdge, 256>>>(src, dst);
    k_zero_stats<<<1, 256>>>();
    k_bnstats<<<256, 256>>>(agg);
    k_bnapply<<<cdiv(Nn * DIMc, 256), 256>>>(agg, n2_g, n2_b, h1, h2);

    // ---- feed-forward ----
    k_split<<<cdiv(Nn * DIMc, 256), 256>>>(h2, Ahi, Alo, Nn * DIMc);
    dim3 gF1(DFFc / 128, cdiv(Nn, 128));
    gemm_mma<true, true><<<gF1, 256, GEMM_SMEM>>>(Ahi, Alo, WTh + OFF_W1, WTl + OFF_W1,
                                                  ff_b1, ff1, Nn, DIMc, DFFc);
    k_split<<<cdiv(Nn * DFFc, 256), 256>>>(ff1, Ahi, Alo, Nn * DFFc);
    dim3 gF2(DIMc / 128, cdiv(Nn, 128));
    gemm_mma<false, false><<<gF2, 256, GEMM_SMEM>>>(Ahi, Alo, WTh + OFF_W2, WTl + OFF_W2,
                                                    nullptr, ff2, Nn, DFFc, DIMc);
    k_zero_stats<<<1, 256>>>();
    k_bnstats<<<256, 256>>>(ff2);
    k_bnapply<<<cdiv(Nn * DIMc, 256), 256>>>(ff2, n3_g, n3_b, h2, out);
}

// round 4
// speedup vs baseline: 1.3339x; 1.0598x over previous
#include <cuda_runtime.h>
#include <cuda_bf16.h>
#include <math.h>
#include <stdint.h>

#define Nn    20000
#define Ee    320000
#define DIMc  256
#define Hh    8
#define EDIMc 32
#define DFFc  1024
#define ETOT  (Ee + Nn)

// ---------------- scratch (device globals; no runtime allocation) ----------
static __device__ float    g_xl [(size_t)Nn * DIMc];
static __device__ float    g_xr [(size_t)Nn * DIMc];
static __device__ float    g_ee [(size_t)ETOT * DIMc];
static __device__ float    g_loop[(size_t)Nn * EDIMc];
static __device__ float    g_cnt[Nn];
static __device__ float    g_sc [(size_t)ETOT * Hh];
static __device__ unsigned g_m  [(size_t)Nn * Hh];
static __device__ float    g_den[(size_t)Nn * Hh];
static __device__ float    g_agg[(size_t)Nn * DIMc];
static __device__ float    g_h1 [(size_t)Nn * DIMc];
static __device__ float    g_h2 [(size_t)Nn * DIMc];
static __device__ float    g_ff1[(size_t)Nn * DFFc];
static __device__ float    g_ff2[(size_t)Nn * DIMc];
static __device__ float    g_sum[DIMc];
static __device__ float    g_sumsq[DIMc];

// K-packed bf16 operands:  A' = [Ah | Al | Ah]  (K' = 3K),  B'T = [Bh | Bh | Bl]
static __device__ __nv_bfloat16 g_Apk[(size_t)Nn * 3 * DFFc];    // max K'=3072
static __device__ __nv_bfloat16 g_EApk[(size_t)ETOT * 128];      // K'=96 padded to 128
// weight pool, [N, K'] row-major each
#define OWL1 0
#define OWR1 196608
#define OWE1 393216
#define OWL2 425984
#define OWR2 622592
#define OWE2 819200
#define OW1  851968
#define OW2  1638400
#define WPK_TOTAL (1638400 + 786432)
static __device__ __nv_bfloat16 g_Wpk[WPK_TOTAL];

// ---------------- PTX helpers ------------------------------------------------
__device__ __forceinline__ uint32_t smem_u32(const void* p) {
    uint32_t a;
    asm("{ .reg .u64 t; cvta.to.shared.u64 t, %1; cvt.u32.u64 %0, t; }"
        : "=r"(a) : "l"(p));
    return a;
}
#define LDSM_X4(r0, r1, r2, r3, addr) \
    asm volatile("ldmatrix.sync.aligned.m8n8.x4.shared.b16 {%0,%1,%2,%3}, [%4];" \
                 : "=r"(r0), "=r"(r1), "=r"(r2), "=r"(r3) : "r"(addr))
#define LDSM_X2(r0, r1, addr) \
    asm volatile("ldmatrix.sync.aligned.m8n8.x2.shared.b16 {%0,%1}, [%2];" \
                 : "=r"(r0), "=r"(r1) : "r"(addr))
#define MMA16816(c, a0, a1, a2, a3, b0, b1) \
    asm volatile("mma.sync.aligned.m16n8k16.row.col.f32.bf16.bf16.f32 " \
                 "{%0,%1,%2,%3}, {%4,%5,%6,%7}, {%8,%9}, {%0,%1,%2,%3};" \
                 : "+f"((c)[0]), "+f"((c)[1]), "+f"((c)[2]), "+f"((c)[3]) \
                 : "r"(a0), "r"(a1), "r"(a2), "r"(a3), "r"(b0), "r"(b1))
__device__ __forceinline__ void cp_cg(uint32_t dst, const void* src, int sz) {
    asm volatile("cp.async.cg.shared.global [%0], [%1], 16, %2;"
                 :: "r"(dst), "l"(src), "r"(sz));
}
#define CP_COMMIT() asm volatile("cp.async.commit_group;" ::: "memory")
#define SMEM_SWZ(b) ((b) ^ (((b) >> 3) & 0x70))

// ---------------- pack kernels -----------------------------------------------
__global__ void k_pack_node(const float* __restrict__ X, __nv_bfloat16* __restrict__ A,
                            int rows, int K) {
    int i = blockIdx.x * blockDim.x + threadIdx.x;
    if (i >= rows * K) return;
    int r = i / K, k = i - r * K;
    float v = X[i];
    __nv_bfloat16 h = __float2bfloat16(v);
    __nv_bfloat16 l = __float2bfloat16(v - __bfloat162float(h));
    size_t b = (size_t)r * (3 * K);
    A[b + k] = h;
    A[b + K + k] = l;
    A[b + 2 * K + k] = h;
}
__global__ void k_pack_ea(const float* __restrict__ ew) {
    int i = blockIdx.x * blockDim.x + threadIdx.x;
    if (i >= ETOT * EDIMc) return;
    int r = i >> 5, k = i & 31;
    float v = (r < Ee) ? ew[i] : g_loop[(size_t)(r - Ee) * EDIMc + k];
    __nv_bfloat16 h = __float2bfloat16(v);
    __nv_bfloat16 l = __float2bfloat16(v - __bfloat162float(h));
    size_t b = (size_t)r * 128;
    g_EApk[b + k]      = h;
    g_EApk[b + 32 + k] = l;
    g_EApk[b + 64 + k] = h;
    g_EApk[b + 96 + k] = __float2bfloat16(0.f);
}
// W[K,N] row-major -> W'T[N, Kp] with [Bh | Bh | Bl] and zero tail if Kp>3K
__global__ void k_packT_w(const float* __restrict__ W, __nv_bfloat16* __restrict__ WT,
                          int K, int N, int Kp) {
    int i = blockIdx.x * blockDim.x + threadIdx.x;
    if (i >= K * N) return;
    int k = i / N, n = i - k * N;
    float v = W[i];
    __nv_bfloat16 h = __float2bfloat16(v);
    __nv_bfloat16 l = __float2bfloat16(v - __bfloat162float(h));
    size_t b = (size_t)n * Kp;
    WT[b + k]         = h;
    WT[b + K + k]     = h;
    WT[b + 2 * K + k] = l;
    if (k < Kp - 3 * K) WT[b + 3 * K + k] = __float2bfloat16(0.f);
}

// ---------------- pipelined bf16 GEMM (K-packed x3 trick) ---------------------
// C[M,Nc] = A'[M,Kp] @ B'  with B given as B'T[Nc,Kp] row-major.
// 128x128 tile, K-chunk 64, 2-stage cp.async, SW128-swizzled smem.
#define GEMM_SMEM_PK 65536

template<bool RELU, bool BIAS>
__global__ void __launch_bounds__(256, 2) gemm_pk(
    const __nv_bfloat16* __restrict__ A, const __nv_bfloat16* __restrict__ BT,
    const float* __restrict__ bias, float* __restrict__ C,
    int M, int Kp, int Nc) {
    extern __shared__ __nv_bfloat16 sm[];
    uint32_t sb = smem_u32(sm);
    int tid  = threadIdx.x;
    int lane = tid & 31;
    int w    = tid >> 5;
    int wr   = w & 1;
    int wc   = w >> 1;
    int row0 = blockIdx.y * 128;
    int col0 = blockIdx.x * 128;

    float acc[4][4][4];
#pragma unroll
    for (int i = 0; i < 4; i++)
#pragma unroll
        for (int j = 0; j < 4; j++)
#pragma unroll
            for (int q = 0; q < 4; q++) acc[i][j][q] = 0.f;

    const int nch = Kp >> 6;

    auto issue = [&](int c, int stage) {
        uint32_t sA = sb + (uint32_t)stage * 32768u;
        uint32_t sB = sA + 16384u;
        int k0 = c << 6;
#pragma unroll
        for (int p = 0; p < 4; p++) {
            int idx = tid + (p << 8);
            int row = idx >> 3, u = idx & 7;
            uint32_t soff = SMEM_SWZ((uint32_t)(row * 128 + u * 16));
            int gr = row0 + row;
            cp_cg(sA + soff, A + (size_t)gr * Kp + k0 + u * 8, gr < M ? 16 : 0);
            cp_cg(sB + soff, BT + (size_t)(col0 + row) * Kp + k0 + u * 8, 16);
        }
        CP_COMMIT();
    };
    auto compute = [&](int stage) {
        uint32_t bA = sb + (uint32_t)stage * 32768u;
        uint32_t bB = bA + 16384u;
#pragma unroll
        for (int ks = 0; ks < 4; ks++) {
            uint32_t a[4][4], b[4][2];
#pragma unroll
            for (int mi = 0; mi < 4; mi++) {
                uint32_t byte = (uint32_t)((wr * 64 + mi * 16 + (lane & 15)) * 128 +
                                           ks * 32 + ((lane >> 4) << 4));
                LDSM_X4(a[mi][0], a[mi][1], a[mi][2], a[mi][3], bA + SMEM_SWZ(byte));
            }
#pragma unroll
            for (int ni = 0; ni < 4; ni++) {
                uint32_t byte = (uint32_t)((wc * 32 + ni * 8 + (lane & 7)) * 128 +
                                           ks * 32 + (((lane >> 3) & 1) << 4));
                LDSM_X2(b[ni][0], b[ni][1], bB + SMEM_SWZ(byte));
            }
#pragma unroll
            for (int mi = 0; mi < 4; mi++)
#pragma unroll
                for (int ni = 0; ni < 4; ni++)
                    MMA16816(acc[mi][ni], a[mi][0], a[mi][1], a[mi][2], a[mi][3],
                             b[ni][0], b[ni][1]);
        }
    };

    issue(0, 0);
    for (int c = 0; c < nch; c++) {
        if (c + 1 < nch) {
            issue(c + 1, (c + 1) & 1);
            asm volatile("cp.async.wait_group 1;" ::: "memory");
        } else {
            asm volatile("cp.async.wait_group 0;" ::: "memory");
        }
        __syncthreads();
        compute(c & 1);
        __syncthreads();
    }

#pragma unroll
    for (int mi = 0; mi < 4; mi++) {
#pragma unroll
        for (int ni = 0; ni < 4; ni++) {
            int r = row0 + wr * 64 + mi * 16 + (lane >> 2);
            int c = col0 + wc * 32 + ni * 8 + (lane & 3) * 2;
            float v0 = acc[mi][ni][0], v1 = acc[mi][ni][1];
            float v2 = acc[mi][ni][2], v3 = acc[mi][ni][3];
            if (BIAS) {
                float b0 = bias[c], b1 = bias[c + 1];
                v0 += b0; v1 += b1; v2 += b0; v3 += b1;
            }
            if (RELU) {
                v0 = fmaxf(v0, 0.f); v1 = fmaxf(v1, 0.f);
                v2 = fmaxf(v2, 0.f); v3 = fmaxf(v3, 0.f);
            }
            if (r < M)     { C[(size_t)r * Nc + c] = v0;       C[(size_t)r * Nc + c + 1] = v1; }
            if (r + 8 < M) { C[(size_t)(r + 8) * Nc + c] = v2; C[(size_t)(r + 8) * Nc + c + 1] = v3; }
        }
    }
}

// ---------------- misc kernels (known-correct) --------------------------------
__device__ __forceinline__ unsigned fenc(float f) {
    unsigned u = __float_as_uint(f);
    return (u & 0x80000000u) ? ~u : (u | 0x80000000u);
}
__device__ __forceinline__ float fdec(unsigned u) {
    return (u & 0x80000000u) ? __uint_as_float(u & 0x7fffffffu) : __uint_as_float(~u);
}
__global__ void k_zero_loop() {
    int i = blockIdx.x * blockDim.x + threadIdx.x;
    if (i < Nn * EDIMc) g_loop[i] = 0.f;
    if (i < Nn)         g_cnt[i]  = 0.f;
}
__global__ void k_zero_gat() {
    int i = blockIdx.x * blockDim.x + threadIdx.x;
    if (i >= Nn * DIMc) return;
    g_agg[i] = 0.f;
    if (i < Nn * Hh) { g_m[i] = 0u; g_den[i] = 0.f; }
}
__global__ void k_zero_stats() {
    int t = threadIdx.x;
    if (t < DIMc) { g_sum[t] = 0.f; g_sumsq[t] = 0.f; }
}
__global__ void k_loop_accum(const int* __restrict__ dst, const float* __restrict__ ew) {
    int w    = (blockIdx.x * blockDim.x + threadIdx.x) >> 5;
    int lane = threadIdx.x & 31;
    if (w >= Ee) return;
    int d = dst[w];
    atomicAdd(&g_loop[d * EDIMc + lane], ew[(size_t)w * EDIMc + lane]);
    if (lane == 0) atomicAdd(&g_cnt[d], 1.f);
}
__global__ void k_loop_div() {
    int i = blockIdx.x * blockDim.x + threadIdx.x;
    if (i >= Nn * EDIMc) return;
    g_loop[i] /= fmaxf(g_cnt[i >> 5], 1.f);
}
__global__ void k_score(const int* __restrict__ src, const int* __restrict__ dst,
                        const float* __restrict__ att) {
    __shared__ float att_s[DIMc];
    if (threadIdx.x < DIMc) att_s[threadIdx.x] = att[threadIdx.x];
    __syncthreads();
    int e    = blockIdx.x * (blockDim.x >> 5) + (threadIdx.x >> 5);
    int lane = threadIdx.x & 31;
    if (e >= ETOT) return;
    int s, d;
    if (e < Ee) { s = src[e]; d = dst[e]; } else { s = e - Ee; d = s; }
    const float* xlp = g_xl + (size_t)s * DIMc;
    const float* xrp = g_xr + (size_t)d * DIMc;
    const float* eep = g_ee + (size_t)e * DIMc;
#pragma unroll
    for (int h = 0; h < Hh; h++) {
        int col = (h << 5) + lane;
        float z = xlp[col] + xrp[col] + eep[col];
        z = (z > 0.f) ? z : 0.2f * z;
        float p = z * att_s[col];
#pragma unroll
        for (int off = 16; off; off >>= 1) p += __shfl_xor_sync(0xffffffffu, p, off);
        if (lane == 0) {
            g_sc[(size_t)e * Hh + h] = p;
            atomicMax(&g_m[d * Hh + h], fenc(p));
        }
    }
}
__global__ void k_expden(const int* __restrict__ dst) {
    int i = blockIdx.x * blockDim.x + threadIdx.x;
    if (i >= ETOT * Hh) return;
    int e = i >> 3, h = i & 7;
    int d = (e < Ee) ? dst[e] : (e - Ee);
    float ex = __expf(g_sc[i] - fdec(g_m[d * Hh + h]));
    g_sc[i] = ex;
    atomicAdd(&g_den[d * Hh + h], ex);
}
__global__ void k_agg(const int* __restrict__ src, const int* __restrict__ dst) {
    int e    = blockIdx.x * (blockDim.x >> 5) + (threadIdx.x >> 5);
    int lane = threadIdx.x & 31;
    if (e >= ETOT) return;
    int s, d;
    if (e < Ee) { s = src[e]; d = dst[e]; } else { s = e - Ee; d = s; }
    const float* xlp = g_xl + (size_t)s * DIMc;
    float* outp = g_agg + (size_t)d * DIMc;
#pragma unroll
    for (int h = 0; h < Hh; h++) {
        float alpha = g_sc[(size_t)e * Hh + h] / g_den[d * Hh + h];
        int col = (h << 5) + lane;
        atomicAdd(&outp[col], alpha * xlp[col]);
    }
}
__global__ void k_bnstats(const float* __restrict__ X) {
    int c = threadIdx.x;
    float s = 0.f, q = 0.f;
    for (int r = blockIdx.x; r < Nn; r += gridDim.x) {
        float v = X[(size_t)r * DIMc + c];
        s += v; q += v * v;
    }
    atomicAdd(&g_sum[c], s);
    atomicAdd(&g_sumsq[c], q);
}
__global__ void k_bnapply(const float* __restrict__ X, const float* __restrict__ gam,
                          const float* __restrict__ bet, const float* __restrict__ res,
                          float* __restrict__ out) {
    int i = blockIdx.x * blockDim.x + threadIdx.x;
    if (i >= Nn * DIMc) return;
    int c = i & (DIMc - 1);
    float mu  = g_sum[c]   * (1.f / Nn);
    float var = g_sumsq[c] * (1.f / Nn) - mu * mu;
    float y = (X[i] - mu) * rsqrtf(var + 1e-5f) * gam[c] + bet[c];
    y = (y > 0.f) ? y : 0.01f * y;
    out[i] = res[i] + y;
}

// ---------------- host orchestration ------------------------------------------
static inline int cdiv(int a, int b) { return (a + b - 1) / b; }

extern "C" void kernel_launch(void* const* d_in, const int* in_sizes, int n_in,
                              void* d_out, int out_size) {
    const float* nf    = (const float*)d_in[0];
    const int*   ei    = (const int*)  d_in[1];
    const float* ew    = (const float*)d_in[2];
    const float* g1_Wl = (const float*)d_in[3];
    const float* g1_Wr = (const float*)d_in[4];
    const float* g1_We = (const float*)d_in[5];
    const float* g1_at = (const float*)d_in[6];
    const float* g2_Wl = (const float*)d_in[8];
    const float* g2_Wr = (const float*)d_in[9];
    const float* g2_We = (const float*)d_in[10];
    const float* g2_at = (const float*)d_in[11];
    const float* n1_g  = (const float*)d_in[13];
    const float* n1_b  = (const float*)d_in[14];
    const float* n2_g  = (const float*)d_in[15];
    const float* n2_b  = (const float*)d_in[16];
    const float* n3_g  = (const float*)d_in[17];
    const float* n3_b  = (const float*)d_in[18];
    const float* ff_W1 = (const float*)d_in[19];
    const float* ff_b1 = (const float*)d_in[20];
    const float* ff_W2 = (const float*)d_in[21];
    const int* src = ei;
    const int* dst = ei + Ee;
    float* out = (float*)d_out;

    void* p;
    cudaGetSymbolAddress(&p, g_xl);   float* xl   = (float*)p;
    cudaGetSymbolAddress(&p, g_xr);   float* xr   = (float*)p;
    cudaGetSymbolAddress(&p, g_ee);   float* ee   = (float*)p;
    cudaGetSymbolAddress(&p, g_agg);  float* agg  = (float*)p;
    cudaGetSymbolAddress(&p, g_h1);   float* h1   = (float*)p;
    cudaGetSymbolAddress(&p, g_h2);   float* h2   = (float*)p;
    cudaGetSymbolAddress(&p, g_ff1);  float* ff1  = (float*)p;
    cudaGetSymbolAddress(&p, g_ff2);  float* ff2  = (float*)p;
    cudaGetSymbolAddress(&p, g_Apk);  __nv_bfloat16* Apk = (__nv_bfloat16*)p;
    cudaGetSymbolAddress(&p, g_EApk); __nv_bfloat16* EApk = (__nv_bfloat16*)p;
    cudaGetSymbolAddress(&p, g_Wpk);  __nv_bfloat16* Wpk = (__nv_bfloat16*)p;

    cudaFuncSetAttribute(gemm_pk<false, false>,
                         cudaFuncAttributeMaxDynamicSharedMemorySize, GEMM_SMEM_PK);
    cudaFuncSetAttribute(gemm_pk<true, true>,
                         cudaFuncAttributeMaxDynamicSharedMemorySize, GEMM_SMEM_PK);

    // ---- weight packs (transpose + hi/lo K-pack) ----
    k_packT_w<<<cdiv(DIMc * DIMc, 256), 256>>>(g1_Wl, Wpk + OWL1, DIMc, DIMc, 768);
    k_packT_w<<<cdiv(DIMc * DIMc, 256), 256>>>(g1_Wr, Wpk + OWR1, DIMc, DIMc, 768);
    k_packT_w<<<cdiv(EDIMc * DIMc, 256), 256>>>(g1_We, Wpk + OWE1, EDIMc, DIMc, 128);
    k_packT_w<<<cdiv(DIMc * DIMc, 256), 256>>>(g2_Wl, Wpk + OWL2, DIMc, DIMc, 768);
    k_packT_w<<<cdiv(DIMc * DIMc, 256), 256>>>(g2_Wr, Wpk + OWR2, DIMc, DIMc, 768);
    k_packT_w<<<cdiv(EDIMc * DIMc, 256), 256>>>(g2_We, Wpk + OWE2, EDIMc, DIMc, 128);
    k_packT_w<<<cdiv(DIMc * DFFc, 256), 256>>>(ff_W1, Wpk + OW1, DIMc, DFFc, 768);
    k_packT_w<<<cdiv(DFFc * DIMc, 256), 256>>>(ff_W2, Wpk + OW2, DFFc, DIMc, 3072);

    // ---- self-loop edge features + edge-attr pack ----
    k_zero_loop<<<cdiv(Nn * EDIMc, 256), 256>>>();
    k_loop_accum<<<cdiv(Ee * 32, 256), 256>>>(dst, ew);
    k_loop_div<<<cdiv(Nn * EDIMc, 256), 256>>>();
    k_pack_ea<<<cdiv(ETOT * EDIMc, 256), 256>>>(ew);

    dim3 gNode(2, cdiv(Nn, 128));
    dim3 gEdge(2, cdiv(ETOT, 128));
    int nbEdge = cdiv(ETOT, 8);

    // ---- block 1 ----
    k_zero_gat<<<cdiv(Nn * DIMc, 256), 256>>>();
    k_pack_node<<<cdiv(Nn * DIMc, 256), 256>>>(nf, Apk, Nn, DIMc);
    gemm_pk<false, false><<<gNode, 256, GEMM_SMEM_PK>>>(Apk, Wpk + OWL1, nullptr, xl, Nn, 768, DIMc);
    gemm_pk<false, false><<<gNode, 256, GEMM_SMEM_PK>>>(Apk, Wpk + OWR1, nullptr, xr, Nn, 768, DIMc);
    gemm_pk<false, false><<<gEdge, 256, GEMM_SMEM_PK>>>(EApk, Wpk + OWE1, nullptr, ee, ETOT, 128, DIMc);
    k_score<<<nbEdge, 256>>>(src, dst, g1_at);
    k_expden<<<cdiv(ETOT * Hh, 256), 256>>>(dst);
    k_agg<<<nbEdge, 256>>>(src, dst);
    k_zero_stats<<<1, 256>>>();
    k_bnstats<<<256, 256>>>(agg);
    k_bnapply<<<cdiv(Nn * DIMc, 256), 256>>>(agg, n1_g, n1_b, nf, h1);

    // ---- block 2 ----
    k_zero_gat<<<cdiv(Nn * DIMc, 256), 256>>>();
    k_pack_node<<<cdiv(Nn * DIMc, 256), 256>>>(h1, Apk, Nn, DIMc);
    gemm_pk<false, false><<<gNode, 256, GEMM_SMEM_PK>>>(Apk, Wpk + OWL2, nullptr, xl, Nn, 768, DIMc);
    gemm_pk<false, false><<<gNode, 256, GEMM_SMEM_PK>>>(Apk, Wpk + OWR2, nullptr, xr, Nn, 768, DIMc);
    gemm_pk<false, false><<<gEdge, 256, GEMM_SMEM_PK>>>(EApk, Wpk + OWE2, nullptr, ee, ETOT, 128, DIMc);
    k_score<<<nbEdge, 256>>>(src, dst, g2_at);
    k_expden<<<cdiv(ETOT * Hh, 256), 256>>>(dst);
    k_agg<<<nbEdge, 256>>>(src, dst);
    k_zero_stats<<<1, 256>>>();
    k_bnstats<<<256, 256>>>(agg);
    k_bnapply<<<cdiv(Nn * DIMc, 256), 256>>>(agg, n2_g, n2_b, h1, h2);

    // ---- feed-forward ----
    k_pack_node<<<cdiv(Nn * DIMc, 256), 256>>>(h2, Apk, Nn, DIMc);
    dim3 gF1(8, cdiv(Nn, 128));
    gemm_pk<true, true><<<gF1, 256, GEMM_SMEM_PK>>>(Apk, Wpk + OW1, ff_b1, ff1, Nn, 768, DFFc);
    k_pack_node<<<cdiv(Nn * DFFc, 256), 256>>>(ff1, Apk, Nn, DFFc);
    dim3 gF2(2, cdiv(Nn, 128));
    gemm_pk<false, false><<<gF2, 256, GEMM_SMEM_PK>>>(Apk, Wpk + OW2, nullptr, ff2, Nn, 3072, DIMc);
    k_zero_stats<<<1, 256>>>();
    k_bnstats<<<256, 256>>>(ff2);
    k_bnapply<<<cdiv(Nn * DIMc, 256), 256>>>(ff2, n3_g, n3_b, h2, out);
}

// round 5
// speedup vs baseline: 1.6019x; 1.2009x over previous
#include <cuda_runtime.h>
#include <cuda_bf16.h>
#include <cuda_fp16.h>
#include <math.h>
#include <stdint.h>

#define Nn    20000
#define Ee    320000
#define DIMc  256
#define Hh    8
#define EDIMc 32
#define DFFc  1024
#define ETOT  (Ee + Nn)

// ---------------- scratch (device globals; no runtime allocation) ----------
static __device__ float    g_xl [(size_t)Nn * DIMc];
static __device__ float    g_xr [(size_t)Nn * DIMc];
static __device__ __half   g_eeh[(size_t)ETOT * DIMc];
static __device__ float    g_loop[(size_t)Nn * EDIMc];
static __device__ float    g_cnt[Nn];
static __device__ float    g_sc [(size_t)ETOT * Hh];
static __device__ float    g_agg[(size_t)Nn * DIMc];
static __device__ float    g_h1 [(size_t)Nn * DIMc];
static __device__ float    g_h2 [(size_t)Nn * DIMc];
static __device__ float    g_ff1[(size_t)Nn * DFFc];
static __device__ float    g_ff2[(size_t)Nn * DIMc];
static __device__ float    g_sum[DIMc];
static __device__ float    g_sumsq[DIMc];
// CSR (built once; graph shared by both layers)
static __device__ int      g_rowptr[Nn + 1];
static __device__ int      g_tmp[Nn];
static __device__ int2     g_adj[Ee];          // {src, edge_id}

// K-packed bf16 operands:  A' = [Ah | Al | Ah]  (K' = 3K),  B'T = [Bh | Bh | Bl]
static __device__ __nv_bfloat16 g_Apk[(size_t)Nn * 3 * DFFc];
static __device__ __nv_bfloat16 g_EApk[(size_t)ETOT * 128];
#define OWL1 0
#define OWR1 196608
#define OWE1 393216
#define OWL2 425984
#define OWR2 622592
#define OWE2 819200
#define OW1  851968
#define OW2  1638400
#define WPK_TOTAL (1638400 + 786432)
static __device__ __nv_bfloat16 g_Wpk[WPK_TOTAL];

// ---------------- PTX helpers ------------------------------------------------
__device__ __forceinline__ uint32_t smem_u32(const void* p) {
    uint32_t a;
    asm("{ .reg .u64 t; cvta.to.shared.u64 t, %1; cvt.u32.u64 %0, t; }"
        : "=r"(a) : "l"(p));
    return a;
}
#define LDSM_X4(r0, r1, r2, r3, addr) \
    asm volatile("ldmatrix.sync.aligned.m8n8.x4.shared.b16 {%0,%1,%2,%3}, [%4];" \
                 : "=r"(r0), "=r"(r1), "=r"(r2), "=r"(r3) : "r"(addr))
#define LDSM_X2(r0, r1, addr) \
    asm volatile("ldmatrix.sync.aligned.m8n8.x2.shared.b16 {%0,%1}, [%2];" \
                 : "=r"(r0), "=r"(r1) : "r"(addr))
#define MMA16816(c, a0, a1, a2, a3, b0, b1) \
    asm volatile("mma.sync.aligned.m16n8k16.row.col.f32.bf16.bf16.f32 " \
                 "{%0,%1,%2,%3}, {%4,%5,%6,%7}, {%8,%9}, {%0,%1,%2,%3};" \
                 : "+f"((c)[0]), "+f"((c)[1]), "+f"((c)[2]), "+f"((c)[3]) \
                 : "r"(a0), "r"(a1), "r"(a2), "r"(a3), "r"(b0), "r"(b1))
__device__ __forceinline__ void cp_cg(uint32_t dst, const void* src, int sz) {
    asm volatile("cp.async.cg.shared.global [%0], [%1], 16, %2;"
                 :: "r"(dst), "l"(src), "r"(sz));
}
#define CP_COMMIT() asm volatile("cp.async.commit_group;" ::: "memory")
#define SMEM_SWZ(b) ((b) ^ (((b) >> 3) & 0x70))

// ---------------- pack kernels -----------------------------------------------
__global__ void k_pack_node(const float* __restrict__ X, __nv_bfloat16* __restrict__ A,
                            int rows, int K) {
    int i = blockIdx.x * blockDim.x + threadIdx.x;
    if (i >= rows * K) return;
    int r = i / K, k = i - r * K;
    float v = X[i];
    __nv_bfloat16 h = __float2bfloat16(v);
    __nv_bfloat16 l = __float2bfloat16(v - __bfloat162float(h));
    size_t b = (size_t)r * (3 * K);
    A[b + k] = h;
    A[b + K + k] = l;
    A[b + 2 * K + k] = h;
}
__global__ void k_pack_ea(const float* __restrict__ ew) {
    int i = blockIdx.x * blockDim.x + threadIdx.x;
    if (i >= ETOT * EDIMc) return;
    int r = i >> 5, k = i & 31;
    float v = (r < Ee) ? ew[i] : g_loop[(size_t)(r - Ee) * EDIMc + k];
    __nv_bfloat16 h = __float2bfloat16(v);
    __nv_bfloat16 l = __float2bfloat16(v - __bfloat162float(h));
    size_t b = (size_t)r * 128;
    g_EApk[b + k]      = h;
    g_EApk[b + 32 + k] = l;
    g_EApk[b + 64 + k] = h;
    g_EApk[b + 96 + k] = __float2bfloat16(0.f);
}
__global__ void k_packT_w(const float* __restrict__ W, __nv_bfloat16* __restrict__ WT,
                          int K, int N, int Kp) {
    int i = blockIdx.x * blockDim.x + threadIdx.x;
    if (i >= K * N) return;
    int k = i / N, n = i - k * N;
    float v = W[i];
    __nv_bfloat16 h = __float2bfloat16(v);
    __nv_bfloat16 l = __float2bfloat16(v - __bfloat162float(h));
    size_t b = (size_t)n * Kp;
    WT[b + k]         = h;
    WT[b + K + k]     = h;
    WT[b + 2 * K + k] = l;
    if (k < Kp - 3 * K) WT[b + 3 * K + k] = __float2bfloat16(0.f);
}

// ---------------- pipelined bf16 GEMM (K-packed x3 trick) ---------------------
#define GEMM_SMEM_PK 65536

template<bool RELU, bool BIAS, bool HOUT>
__global__ void __launch_bounds__(256, 2) gemm_pk(
    const __nv_bfloat16* __restrict__ A, const __nv_bfloat16* __restrict__ BT,
    const float* __restrict__ bias, float* __restrict__ C,
    int M, int Kp, int Nc) {
    extern __shared__ __nv_bfloat16 sm[];
    uint32_t sb = smem_u32(sm);
    int tid  = threadIdx.x;
    int lane = tid & 31;
    int w    = tid >> 5;
    int wr   = w & 1;
    int wc   = w >> 1;
    int row0 = blockIdx.y * 128;
    int col0 = blockIdx.x * 128;

    float acc[4][4][4];
#pragma unroll
    for (int i = 0; i < 4; i++)
#pragma unroll
        for (int j = 0; j < 4; j++)
#pragma unroll
            for (int q = 0; q < 4; q++) acc[i][j][q] = 0.f;

    const int nch = Kp >> 6;

    auto issue = [&](int c, int stage) {
        uint32_t sA = sb + (uint32_t)stage * 32768u;
        uint32_t sB = sA + 16384u;
        int k0 = c << 6;
#pragma unroll
        for (int p = 0; p < 4; p++) {
            int idx = tid + (p << 8);
            int row = idx >> 3, u = idx & 7;
            uint32_t soff = SMEM_SWZ((uint32_t)(row * 128 + u * 16));
            int gr = row0 + row;
            cp_cg(sA + soff, A + (size_t)gr * Kp + k0 + u * 8, gr < M ? 16 : 0);
            cp_cg(sB + soff, BT + (size_t)(col0 + row) * Kp + k0 + u * 8, 16);
        }
        CP_COMMIT();
    };
    auto compute = [&](int stage) {
        uint32_t bA = sb + (uint32_t)stage * 32768u;
        uint32_t bB = bA + 16384u;
#pragma unroll
        for (int ks = 0; ks < 4; ks++) {
            uint32_t a[4][4], b[4][2];
#pragma unroll
            for (int mi = 0; mi < 4; mi++) {
                uint32_t byte = (uint32_t)((wr * 64 + mi * 16 + (lane & 15)) * 128 +
                                           ks * 32 + ((lane >> 4) << 4));
                LDSM_X4(a[mi][0], a[mi][1], a[mi][2], a[mi][3], bA + SMEM_SWZ(byte));
            }
#pragma unroll
            for (int ni = 0; ni < 4; ni++) {
                uint32_t byte = (uint32_t)((wc * 32 + ni * 8 + (lane & 7)) * 128 +
                                           ks * 32 + (((lane >> 3) & 1) << 4));
                LDSM_X2(b[ni][0], b[ni][1], bB + SMEM_SWZ(byte));
            }
#pragma unroll
            for (int mi = 0; mi < 4; mi++)
#pragma unroll
                for (int ni = 0; ni < 4; ni++)
                    MMA16816(acc[mi][ni], a[mi][0], a[mi][1], a[mi][2], a[mi][3],
                             b[ni][0], b[ni][1]);
        }
    };

    issue(0, 0);
    for (int c = 0; c < nch; c++) {
        if (c + 1 < nch) {
            issue(c + 1, (c + 1) & 1);
            asm volatile("cp.async.wait_group 1;" ::: "memory");
        } else {
            asm volatile("cp.async.wait_group 0;" ::: "memory");
        }
        __syncthreads();
        compute(c & 1);
        __syncthreads();
    }

#pragma unroll
    for (int mi = 0; mi < 4; mi++) {
#pragma unroll
        for (int ni = 0; ni < 4; ni++) {
            int r = row0 + wr * 64 + mi * 16 + (lane >> 2);
            int c = col0 + wc * 32 + ni * 8 + (lane & 3) * 2;
            float v0 = acc[mi][ni][0], v1 = acc[mi][ni][1];
            float v2 = acc[mi][ni][2], v3 = acc[mi][ni][3];
            if (BIAS) {
                float b0 = bias[c], b1 = bias[c + 1];
                v0 += b0; v1 += b1; v2 += b0; v3 += b1;
            }
            if (RELU) {
                v0 = fmaxf(v0, 0.f); v1 = fmaxf(v1, 0.f);
                v2 = fmaxf(v2, 0.f); v3 = fmaxf(v3, 0.f);
            }
            if (HOUT) {
                __half* Ch = (__half*)C;
                if (r < M)     *(__half2*)(Ch + (size_t)r * Nc + c)       = __floats2half2_rn(v0, v1);
                if (r + 8 < M) *(__half2*)(Ch + (size_t)(r + 8) * Nc + c) = __floats2half2_rn(v2, v3);
            } else {
                if (r < M)     { C[(size_t)r * Nc + c] = v0;       C[(size_t)r * Nc + c + 1] = v1; }
                if (r + 8 < M) { C[(size_t)(r + 8) * Nc + c] = v2; C[(size_t)(r + 8) * Nc + c + 1] = v3; }
            }
        }
    }
}

// ---------------- self-loop mean + CSR build ----------------------------------
__global__ void k_zero_loop() {
    int i = blockIdx.x * blockDim.x + threadIdx.x;
    if (i < Nn * EDIMc) g_loop[i] = 0.f;
    if (i < Nn)         g_cnt[i]  = 0.f;
}
__global__ void k_loop_accum(const int* __restrict__ dst, const float* __restrict__ ew) {
    int w    = (blockIdx.x * blockDim.x + threadIdx.x) >> 5;
    int lane = threadIdx.x & 31;
    if (w >= Ee) return;
    int d = dst[w];
    atomicAdd(&g_loop[d * EDIMc + lane], ew[(size_t)w * EDIMc + lane]);
    if (lane == 0) atomicAdd(&g_cnt[d], 1.f);
}
__global__ void k_loop_div() {
    int i = blockIdx.x * blockDim.x + threadIdx.x;
    if (i >= Nn * EDIMc) return;
    g_loop[i] /= fmaxf(g_cnt[i >> 5], 1.f);
}
__global__ void k_scan() {           // single block, 1024 threads
    __shared__ int part[1024];
    int t = threadIdx.x;
    const int SEG = (Nn + 1023) / 1024;
    int base = t * SEG;
    int s = 0;
    for (int i = 0; i < SEG; i++) {
        int idx = base + i;
        if (idx < Nn) s += (int)g_cnt[idx];
    }
    part[t] = s;
    __syncthreads();
    for (int off = 1; off < 1024; off <<= 1) {
        int v = (t >= off) ? part[t - off] : 0;
        __syncthreads();
        part[t] += v;
        __syncthreads();
    }
    int run = (t == 0) ? 0 : part[t - 1];
    for (int i = 0; i < SEG; i++) {
        int idx = base + i;
        if (idx < Nn) {
            g_rowptr[idx] = run;
            g_tmp[idx] = run;
            run += (int)g_cnt[idx];
        }
    }
    if (t == 1023) g_rowptr[Nn] = run;
}
__global__ void k_scatter(const int* __restrict__ src, const int* __restrict__ dst) {
    int e = blockIdx.x * blockDim.x + threadIdx.x;
    if (e >= Ee) return;
    int pos = atomicAdd(&g_tmp[dst[e]], 1);
    g_adj[pos] = make_int2(src[e], e);
}

// ---------------- GATv2 edge score (no atomics) --------------------------------
__global__ void k_score(const int* __restrict__ src, const int* __restrict__ dst,
                        const float* __restrict__ att) {
    __shared__ float att_s[DIMc];
    if (threadIdx.x < DIMc) att_s[threadIdx.x] = att[threadIdx.x];
    __syncthreads();
    int e    = blockIdx.x * (blockDim.x >> 5) + (threadIdx.x >> 5);
    int lane = threadIdx.x & 31;
    if (e >= ETOT) return;
    int s, d;
    if (e < Ee) { s = src[e]; d = dst[e]; } else { s = e - Ee; d = s; }
    const float*  xlp = g_xl + (size_t)s * DIMc;
    const float*  xrp = g_xr + (size_t)d * DIMc;
    const __half* eep = g_eeh + (size_t)e * DIMc;
#pragma unroll
    for (int h = 0; h < Hh; h++) {
        int col = (h << 5) + lane;
        float z = xlp[col] + xrp[col] + __half2float(eep[col]);
        z = (z > 0.f) ? z : 0.2f * z;
        float p = z * att_s[col];
#pragma unroll
        for (int off = 16; off; off >>= 1) p += __shfl_xor_sync(0xffffffffu, p, off);
        if (lane == 0) g_sc[(size_t)e * Hh + h] = p;
    }
}

// ---------------- per-node fused softmax + aggregation (warp per node) --------
__global__ void k_node(const int* __restrict__ dummy) {
    int d    = blockIdx.x * 8 + (threadIdx.x >> 5);
    int lane = threadIdx.x & 31;
    if (d >= Nn) return;
    int beg = g_rowptr[d], end = g_rowptr[d + 1];
    const float* ssc = g_sc + (size_t)(Ee + d) * Hh;   // self-loop scores

    // per-head max (init with self-loop)
    float mx[Hh];
#pragma unroll
    for (int h = 0; h < Hh; h++) mx[h] = ssc[h];
    for (int i = beg + lane; i < end; i += 32) {
        const float* sc = g_sc + (size_t)g_adj[i].y * Hh;
#pragma unroll
        for (int h = 0; h < Hh; h++) mx[h] = fmaxf(mx[h], sc[h]);
    }
#pragma unroll
    for (int off = 16; off; off >>= 1)
#pragma unroll
        for (int h = 0; h < Hh; h++)
            mx[h] = fmaxf(mx[h], __shfl_xor_sync(0xffffffffu, mx[h], off));

    // per-head denominator
    float dn[Hh];
#pragma unroll
    for (int h = 0; h < Hh; h++) dn[h] = 0.f;
    for (int i = beg + lane; i < end; i += 32) {
        const float* sc = g_sc + (size_t)g_adj[i].y * Hh;
#pragma unroll
        for (int h = 0; h < Hh; h++) dn[h] += __expf(sc[h] - mx[h]);
    }
#pragma unroll
    for (int off = 16; off; off >>= 1)
#pragma unroll
        for (int h = 0; h < Hh; h++)
            dn[h] += __shfl_xor_sync(0xffffffffu, dn[h], off);
#pragma unroll
    for (int h = 0; h < Hh; h++) dn[h] = 1.f / (dn[h] + __expf(ssc[h] - mx[h]));

    // aggregation: lane covers cols [8*lane, 8*lane+8), single head h=lane>>2
    int hh = lane >> 2;
    int c0 = lane << 3;
    float m_h = mx[hh], inv_h = dn[hh];

    float acc[8];
    {
        float a = __expf(ssc[hh] - m_h) * inv_h;
        const float4* xp = (const float4*)(g_xl + (size_t)d * DIMc + c0);
        float4 u0 = xp[0], u1 = xp[1];
        acc[0] = a * u0.x; acc[1] = a * u0.y; acc[2] = a * u0.z; acc[3] = a * u0.w;
        acc[4] = a * u1.x; acc[5] = a * u1.y; acc[6] = a * u1.z; acc[7] = a * u1.w;
    }
    for (int i = beg; i < end; i++) {
        int2 se = g_adj[i];
        float a = __expf(g_sc[(size_t)se.y * Hh + hh] - m_h) * inv_h;
        const float4* xp = (const float4*)(g_xl + (size_t)se.x * DIMc + c0);
        float4 u0 = xp[0], u1 = xp[1];
        acc[0] += a * u0.x; acc[1] += a * u0.y; acc[2] += a * u0.z; acc[3] += a * u0.w;
        acc[4] += a * u1.x; acc[5] += a * u1.y; acc[6] += a * u1.z; acc[7] += a * u1.w;
    }
    float4* op = (float4*)(g_agg + (size_t)d * DIMc + c0);
    op[0] = make_float4(acc[0], acc[1], acc[2], acc[3]);
    op[1] = make_float4(acc[4], acc[5], acc[6], acc[7]);
}

// ---------------- BatchNorm ----------------------------------------------------
__global__ void k_zero_stats() {
    int t = threadIdx.x;
    if (t < DIMc) { g_sum[t] = 0.f; g_sumsq[t] = 0.f; }
}
__global__ void k_bnstats(const float* __restrict__ X) {
    int c = threadIdx.x;
    float s = 0.f, q = 0.f;
    for (int r = blockIdx.x; r < Nn; r += gridDim.x) {
        float v = X[(size_t)r * DIMc + c];
        s += v; q += v * v;
    }
    atomicAdd(&g_sum[c], s);
    atomicAdd(&g_sumsq[c], q);
}
__global__ void k_bnapply(const float* __restrict__ X, const float* __restrict__ gam,
                          const float* __restrict__ bet, const float* __restrict__ res,
                          float* __restrict__ out) {
    int i = blockIdx.x * blockDim.x + threadIdx.x;
    if (i >= Nn * DIMc) return;
    int c = i & (DIMc - 1);
    float mu  = g_sum[c]   * (1.f / Nn);
    float var = g_sumsq[c] * (1.f / Nn) - mu * mu;
    float y = (X[i] - mu) * rsqrtf(var + 1e-5f) * gam[c] + bet[c];
    y = (y > 0.f) ? y : 0.01f * y;
    out[i] = res[i] + y;
}

// ---------------- host orchestration -------------------------------------------
static inline int cdiv(int a, int b) { return (a + b - 1) / b; }

extern "C" void kernel_launch(void* const* d_in, const int* in_sizes, int n_in,
                              void* d_out, int out_size) {
    const float* nf    = (const float*)d_in[0];
    const int*   ei    = (const int*)  d_in[1];
    const float* ew    = (const float*)d_in[2];
    const float* g1_Wl = (const float*)d_in[3];
    const float* g1_Wr = (const float*)d_in[4];
    const float* g1_We = (const float*)d_in[5];
    const float* g1_at = (const float*)d_in[6];
    const float* g2_Wl = (const float*)d_in[8];
    const float* g2_Wr = (const float*)d_in[9];
    const float* g2_We = (const float*)d_in[10];
    const float* g2_at = (const float*)d_in[11];
    const float* n1_g  = (const float*)d_in[13];
    const float* n1_b  = (const float*)d_in[14];
    const float* n2_g  = (const float*)d_in[15];
    const float* n2_b  = (const float*)d_in[16];
    const float* n3_g  = (const float*)d_in[17];
    const float* n3_b  = (const float*)d_in[18];
    const float* ff_W1 = (const float*)d_in[19];
    const float* ff_b1 = (const float*)d_in[20];
    const float* ff_W2 = (const float*)d_in[21];
    const int* src = ei;
    const int* dst = ei + Ee;
    float* out = (float*)d_out;

    void* p;
    cudaGetSymbolAddress(&p, g_xl);   float* xl   = (float*)p;
    cudaGetSymbolAddress(&p, g_xr);   float* xr   = (float*)p;
    cudaGetSymbolAddress(&p, g_eeh);  float* eeh  = (float*)p;   // cast inside GEMM
    cudaGetSymbolAddress(&p, g_agg);  float* agg  = (float*)p;
    cudaGetSymbolAddress(&p, g_h1);   float* h1   = (float*)p;
    cudaGetSymbolAddress(&p, g_h2);   float* h2   = (float*)p;
    cudaGetSymbolAddress(&p, g_ff1);  float* ff1  = (float*)p;
    cudaGetSymbolAddress(&p, g_ff2);  float* ff2  = (float*)p;
    cudaGetSymbolAddress(&p, g_Apk);  __nv_bfloat16* Apk = (__nv_bfloat16*)p;
    cudaGetSymbolAddress(&p, g_EApk); __nv_bfloat16* EApk = (__nv_bfloat16*)p;
    cudaGetSymbolAddress(&p, g_Wpk);  __nv_bfloat16* Wpk = (__nv_bfloat16*)p;

    cudaFuncSetAttribute(gemm_pk<false, false, false>,
                         cudaFuncAttributeMaxDynamicSharedMemorySize, GEMM_SMEM_PK);
    cudaFuncSetAttribute(gemm_pk<true, true, false>,
                         cudaFuncAttributeMaxDynamicSharedMemorySize, GEMM_SMEM_PK);
    cudaFuncSetAttribute(gemm_pk<false, false, true>,
                         cudaFuncAttributeMaxDynamicSharedMemorySize, GEMM_SMEM_PK);

    // ---- weight packs ----
    k_packT_w<<<cdiv(DIMc * DIMc, 256), 256>>>(g1_Wl, Wpk + OWL1, DIMc, DIMc, 768);
    k_packT_w<<<cdiv(DIMc * DIMc, 256), 256>>>(g1_Wr, Wpk + OWR1, DIMc, DIMc, 768);
    k_packT_w<<<cdiv(EDIMc * DIMc, 256), 256>>>(g1_We, Wpk + OWE1, EDIMc, DIMc, 128);
    k_packT_w<<<cdiv(DIMc * DIMc, 256), 256>>>(g2_Wl, Wpk + OWL2, DIMc, DIMc, 768);
    k_packT_w<<<cdiv(DIMc * DIMc, 256), 256>>>(g2_Wr, Wpk + OWR2, DIMc, DIMc, 768);
    k_packT_w<<<cdiv(EDIMc * DIMc, 256), 256>>>(g2_We, Wpk + OWE2, EDIMc, DIMc, 128);
    k_packT_w<<<cdiv(DIMc * DFFc, 256), 256>>>(ff_W1, Wpk + OW1, DIMc, DFFc, 768);
    k_packT_w<<<cdiv(DFFc * DIMc, 256), 256>>>(ff_W2, Wpk + OW2, DFFc, DIMc, 3072);

    // ---- self-loop edge features + CSR build (once; shared by both layers) ----
    k_zero_loop<<<cdiv(Nn * EDIMc, 256), 256>>>();
    k_loop_accum<<<cdiv(Ee * 32, 256), 256>>>(dst, ew);
    k_loop_div<<<cdiv(Nn * EDIMc, 256), 256>>>();
    k_scan<<<1, 1024>>>();
    k_scatter<<<cdiv(Ee, 256), 256>>>(src, dst);
    k_pack_ea<<<cdiv(ETOT * EDIMc, 256), 256>>>(ew);

    dim3 gNode(2, cdiv(Nn, 128));
    dim3 gEdge(2, cdiv(ETOT, 128));
    int nbScore = cdiv(ETOT, 8);
    int nbNode  = cdiv(Nn, 8);

    // ---- block 1 ----
    k_pack_node<<<cdiv(Nn * DIMc, 256), 256>>>(nf, Apk, Nn, DIMc);
    gemm_pk<false, false, false><<<gNode, 256, GEMM_SMEM_PK>>>(Apk, Wpk + OWL1, nullptr, xl, Nn, 768, DIMc);
    gemm_pk<false, false, false><<<gNode, 256, GEMM_SMEM_PK>>>(Apk, Wpk + OWR1, nullptr, xr, Nn, 768, DIMc);
    gemm_pk<false, false, true ><<<gEdge, 256, GEMM_SMEM_PK>>>(EApk, Wpk + OWE1, nullptr, eeh, ETOT, 128, DIMc);
    k_score<<<nbScore, 256>>>(src, dst, g1_at);
    k_node<<<nbNode, 256>>>(nullptr);
    k_zero_stats<<<1, 256>>>();
    k_bnstats<<<256, 256>>>(agg);
    k_bnapply<<<cdiv(Nn * DIMc, 256), 256>>>(agg, n1_g, n1_b, nf, h1);

    // ---- block 2 ----
    k_pack_node<<<cdiv(Nn * DIMc, 256), 256>>>(h1, Apk, Nn, DIMc);
    gemm_pk<false, false, false><<<gNode, 256, GEMM_SMEM_PK>>>(Apk, Wpk + OWL2, nullptr, xl, Nn, 768, DIMc);
    gemm_pk<false, false, false><<<gNode, 256, GEMM_SMEM_PK>>>(Apk, Wpk + OWR2, nullptr, xr, Nn, 768, DIMc);
    gemm_pk<false, false, true ><<<gEdge, 256, GEMM_SMEM_PK>>>(EApk, Wpk + OWE2, nullptr, eeh, ETOT, 128, DIMc);
    k_score<<<nbScore, 256>>>(src, dst, g2_at);
    k_node<<<nbNode, 256>>>(nullptr);
    k_zero_stats<<<1, 256>>>();
    k_bnstats<<<256, 256>>>(agg);
    k_bnapply<<<cdiv(Nn * DIMc, 256), 256>>>(agg, n2_g, n2_b, h1, h2);

    // ---- feed-forward ----
    k_pack_node<<<cdiv(Nn * DIMc, 256), 256>>>(h2, Apk, Nn, DIMc);
    dim3 gF1(8, cdiv(Nn, 128));
    gemm_pk<true, true, false><<<gF1, 256, GEMM_SMEM_PK>>>(Apk, Wpk + OW1, ff_b1, ff1, Nn, 768, DFFc);
    k_pack_node<<<cdiv(Nn * DFFc, 256), 256>>>(ff1, Apk, Nn, DFFc);
    dim3 gF2(2, cdiv(Nn, 128));
    gemm_pk<false, false, false><<<gF2, 256, GEMM_SMEM_PK>>>(Apk, Wpk + OW2, nullptr, ff2, Nn, 3072, DIMc);
    k_zero_stats<<<1, 256>>>();
    k_bnstats<<<256, 256>>>(ff2);
    k_bnapply<<<cdiv(Nn * DIMc, 256), 256>>>(ff2, n3_g, n3_b, h2, out);
}

// round 6
// speedup vs baseline: 1.8395x; 1.1483x over previous
#include <cuda_runtime.h>
#include <cuda_bf16.h>
#include <math.h>
#include <stdint.h>

#define Nn    20000
#define Ee    320000
#define DIMc  256
#define Hh    8
#define EDIMc 32
#define DFFc  1024
#define ETOT  (Ee + Nn)

// ---------------- scratch (device globals) -----------------------------------
static __device__ float    g_xlr[(size_t)Nn * 512];        // [xl | xr]
static __device__ float    g_loop[(size_t)Nn * EDIMc];
static __device__ float    g_cnt[Nn];
static __device__ float    g_sc [(size_t)ETOT * Hh];
static __device__ float    g_agg[(size_t)Nn * DIMc];
static __device__ float    g_h1 [(size_t)Nn * DIMc];
static __device__ float    g_h2 [(size_t)Nn * DIMc];
static __device__ float    g_ff2[(size_t)Nn * DIMc];
static __device__ float    g_sum[DIMc];
static __device__ float    g_sumsq[DIMc];
// CSR
static __device__ int      g_rowptr[Nn + 1];
static __device__ int      g_tmp[Nn];
static __device__ int2     g_adj[Ee];

// packed bf16 operands
static __device__ __nv_bfloat16 g_Apk[(size_t)Nn * 768];     // node features, Kp=768
static __device__ __nv_bfloat16 g_Fpk[(size_t)Nn * 3072];    // ff1, Kp=3072
static __device__ __nv_bfloat16 g_EApk[(size_t)ETOT * 128];  // edge attrs, Kp=128
// weight pool [N, Kp] each
#define OWLR1 0
#define OWE1  393216
#define OWLR2 425984
#define OWE2  819200
#define OW1   851968
#define OW2   1638400
#define WPK_TOTAL 2424832
static __device__ __nv_bfloat16 g_Wpk[WPK_TOTAL];

// ---------------- PTX helpers --------------------------------------------------
__device__ __forceinline__ uint32_t smem_u32(const void* p) {
    uint32_t a;
    asm("{ .reg .u64 t; cvta.to.shared.u64 t, %1; cvt.u32.u64 %0, t; }"
        : "=r"(a) : "l"(p));
    return a;
}
#define LDSM_X4(r0, r1, r2, r3, addr) \
    asm volatile("ldmatrix.sync.aligned.m8n8.x4.shared.b16 {%0,%1,%2,%3}, [%4];" \
                 : "=r"(r0), "=r"(r1), "=r"(r2), "=r"(r3) : "r"(addr))
#define LDSM_X2(r0, r1, addr) \
    asm volatile("ldmatrix.sync.aligned.m8n8.x2.shared.b16 {%0,%1}, [%2];" \
                 : "=r"(r0), "=r"(r1) : "r"(addr))
#define MMA16816(c, a0, a1, a2, a3, b0, b1) \
    asm volatile("mma.sync.aligned.m16n8k16.row.col.f32.bf16.bf16.f32 " \
                 "{%0,%1,%2,%3}, {%4,%5,%6,%7}, {%8,%9}, {%0,%1,%2,%3};" \
                 : "+f"((c)[0]), "+f"((c)[1]), "+f"((c)[2]), "+f"((c)[3]) \
                 : "r"(a0), "r"(a1), "r"(a2), "r"(a3), "r"(b0), "r"(b1))
__device__ __forceinline__ void cp_cg(uint32_t dst, const void* src, int sz) {
    asm volatile("cp.async.cg.shared.global [%0], [%1], 16, %2;"
                 :: "r"(dst), "l"(src), "r"(sz));
}
#define CP_COMMIT() asm volatile("cp.async.commit_group;" ::: "memory")
#define SMEM_SWZ(b) ((b) ^ (((b) >> 3) & 0x70))

// ---------------- pack kernels --------------------------------------------------
__global__ void k_pack_node(const float* __restrict__ X, __nv_bfloat16* __restrict__ A,
                            int rows, int K) {
    int i = blockIdx.x * blockDim.x + threadIdx.x;
    if (i >= rows * K) return;
    int r = i / K, k = i - r * K;
    float v = X[i];
    __nv_bfloat16 h = __float2bfloat16(v);
    __nv_bfloat16 l = __float2bfloat16(v - __bfloat162float(h));
    size_t b = (size_t)r * (3 * K);
    A[b + k] = h;
    A[b + K + k] = l;
    A[b + 2 * K + k] = h;
}
__global__ void k_pack_ea(const float* __restrict__ ew) {
    int i = blockIdx.x * blockDim.x + threadIdx.x;
    if (i >= ETOT * EDIMc) return;
    int r = i >> 5, k = i & 31;
    float v = (r < Ee) ? ew[i] : g_loop[(size_t)(r - Ee) * EDIMc + k];
    __nv_bfloat16 h = __float2bfloat16(v);
    __nv_bfloat16 l = __float2bfloat16(v - __bfloat162float(h));
    size_t b = (size_t)r * 128;
    g_EApk[b + k]      = h;
    g_EApk[b + 32 + k] = l;
    g_EApk[b + 64 + k] = h;
    g_EApk[b + 96 + k] = __float2bfloat16(0.f);
}
__global__ void k_packT_w(const float* __restrict__ W, __nv_bfloat16* __restrict__ WT,
                          int K, int N, int Kp) {
    int i = blockIdx.x * blockDim.x + threadIdx.x;
    if (i >= K * N) return;
    int k = i / N, n = i - k * N;
    float v = W[i];
    __nv_bfloat16 h = __float2bfloat16(v);
    __nv_bfloat16 l = __float2bfloat16(v - __bfloat162float(h));
    size_t b = (size_t)n * Kp;
    WT[b + k]         = h;
    WT[b + K + k]     = h;
    WT[b + 2 * K + k] = l;
    if (k < Kp - 3 * K) WT[b + 3 * K + k] = __float2bfloat16(0.f);
}

// ---------------- pipelined bf16 GEMM (K-packed x3) ----------------------------
// EPI: 0 = fp32 out; 1 = relu+bias then write [hi|lo|hi] pack into g_Fpk (Nc=1024)
#define GEMM_SMEM_PK 65536

template<int EPI>
__global__ void __launch_bounds__(256, 2) gemm_pk(
    const __nv_bfloat16* __restrict__ A, const __nv_bfloat16* __restrict__ BT,
    const float* __restrict__ bias, float* __restrict__ C,
    int M, int Kp, int Nc) {
    extern __shared__ __nv_bfloat16 sm[];
    uint32_t sb = smem_u32(sm);
    int tid  = threadIdx.x;
    int lane = tid & 31;
    int w    = tid >> 5;
    int wr   = w & 1;
    int wc   = w >> 1;
    int row0 = blockIdx.y * 128;
    int col0 = blockIdx.x * 128;

    float acc[4][4][4];
#pragma unroll
    for (int i = 0; i < 4; i++)
#pragma unroll
        for (int j = 0; j < 4; j++)
#pragma unroll
            for (int q = 0; q < 4; q++) acc[i][j][q] = 0.f;

    const int nch = Kp >> 6;

    auto issue = [&](int c, int stage) {
        uint32_t sA = sb + (uint32_t)stage * 32768u;
        uint32_t sB = sA + 16384u;
        int k0 = c << 6;
#pragma unroll
        for (int p = 0; p < 4; p++) {
            int idx = tid + (p << 8);
            int row = idx >> 3, u = idx & 7;
            uint32_t soff = SMEM_SWZ((uint32_t)(row * 128 + u * 16));
            int gr = row0 + row;
            cp_cg(sA + soff, A + (size_t)gr * Kp + k0 + u * 8, gr < M ? 16 : 0);
            cp_cg(sB + soff, BT + (size_t)(col0 + row) * Kp + k0 + u * 8, 16);
        }
        CP_COMMIT();
    };
    auto compute = [&](int stage) {
        uint32_t bA = sb + (uint32_t)stage * 32768u;
        uint32_t bB = bA + 16384u;
#pragma unroll
        for (int ks = 0; ks < 4; ks++) {
            uint32_t a[4][4], b[4][2];
#pragma unroll
            for (int mi = 0; mi < 4; mi++) {
                uint32_t byte = (uint32_t)((wr * 64 + mi * 16 + (lane & 15)) * 128 +
                                           ks * 32 + ((lane >> 4) << 4));
                LDSM_X4(a[mi][0], a[mi][1], a[mi][2], a[mi][3], bA + SMEM_SWZ(byte));
            }
#pragma unroll
            for (int ni = 0; ni < 4; ni++) {
                uint32_t byte = (uint32_t)((wc * 32 + ni * 8 + (lane & 7)) * 128 +
                                           ks * 32 + (((lane >> 3) & 1) << 4));
                LDSM_X2(b[ni][0], b[ni][1], bB + SMEM_SWZ(byte));
            }
#pragma unroll
            for (int mi = 0; mi < 4; mi++)
#pragma unroll
                for (int ni = 0; ni < 4; ni++)
                    MMA16816(acc[mi][ni], a[mi][0], a[mi][1], a[mi][2], a[mi][3],
                             b[ni][0], b[ni][1]);
        }
    };

    issue(0, 0);
    for (int c = 0; c < nch; c++) {
        if (c + 1 < nch) {
            issue(c + 1, (c + 1) & 1);
            asm volatile("cp.async.wait_group 1;" ::: "memory");
        } else {
            asm volatile("cp.async.wait_group 0;" ::: "memory");
        }
        __syncthreads();
        compute(c & 1);
        __syncthreads();
    }

#pragma unroll
    for (int mi = 0; mi < 4; mi++) {
#pragma unroll
        for (int ni = 0; ni < 4; ni++) {
            int r = row0 + wr * 64 + mi * 16 + (lane >> 2);
            int c = col0 + wc * 32 + ni * 8 + (lane & 3) * 2;
            float v0 = acc[mi][ni][0], v1 = acc[mi][ni][1];
            float v2 = acc[mi][ni][2], v3 = acc[mi][ni][3];
            if (EPI == 1) {
                float b0 = bias[c], b1 = bias[c + 1];
                v0 = fmaxf(v0 + b0, 0.f); v1 = fmaxf(v1 + b1, 0.f);
                v2 = fmaxf(v2 + b0, 0.f); v3 = fmaxf(v3 + b1, 0.f);
                __nv_bfloat16* P = g_Fpk;
#pragma unroll
                for (int hh = 0; hh < 2; hh++) {
                    int rr = r + hh * 8;
                    if (rr >= M) continue;
                    float u0 = hh ? v2 : v0, u1 = hh ? v3 : v1;
                    size_t base = (size_t)rr * 3072 + c;
                    __nv_bfloat16 h0 = __float2bfloat16(u0);
                    __nv_bfloat16 h1 = __float2bfloat16(u1);
                    P[base]          = h0;
                    P[base + 1]      = h1;
                    P[base + 1024]   = __float2bfloat16(u0 - __bfloat162float(h0));
                    P[base + 1025]   = __float2bfloat16(u1 - __bfloat162float(h1));
                    P[base + 2048]   = h0;
                    P[base + 2049]   = h1;
                }
            } else {
                if (r < M)     { C[(size_t)r * Nc + c] = v0;       C[(size_t)r * Nc + c + 1] = v1; }
                if (r + 8 < M) { C[(size_t)(r + 8) * Nc + c] = v2; C[(size_t)(r + 8) * Nc + c + 1] = v3; }
            }
        }
    }
}

// ---------------- ee GEMM fused with GATv2 score --------------------------------
// Tile: 128 edges x 256 cols, Kp=128 fully smem-resident.
// smem: A 2x16KB @0, B 2x32KB @32768, sc 4KB @98304, att 1KB @102400, src/dst @103424
#define SC_SMEM 104448

__global__ void __launch_bounds__(256, 1) gemm_score(
    const __nv_bfloat16* __restrict__ A, const __nv_bfloat16* __restrict__ BT,
    const float* __restrict__ att,
    const int* __restrict__ src, const int* __restrict__ dst) {
    extern __shared__ char smc[];
    uint32_t sb = smem_u32(smc);
    float* sc_s  = (float*)(smc + 98304);
    float* att_s = (float*)(smc + 102400);
    int*   ss_s  = (int*)(smc + 103424);
    int*   sd_s  = (int*)(smc + 103936);
    int tid = threadIdx.x, lane = tid & 31, w = tid >> 5;
    int wr = w & 1, wc = w >> 1;
    int row0 = blockIdx.x * 128;

    att_s[tid] = att[tid];
    if (tid < 128) {
        int e = row0 + tid;
        int s, d;
        if (e < Ee)       { s = src[e]; d = dst[e]; }
        else if (e < ETOT){ s = e - Ee; d = s; }
        else              { s = 0; d = 0; }
        ss_s[tid] = s; sd_s[tid] = d;
    }
    // async loads: A (2048 x 16B), B (4096 x 16B)
#pragma unroll
    for (int p = 0; p < 8; p++) {
        int i = tid + (p << 8);
        int c = i >> 10, j = i & 1023;
        int row = j >> 3, u = j & 7;
        uint32_t soff = (uint32_t)c * 16384u + SMEM_SWZ((uint32_t)(row * 128 + u * 16));
        int gr = row0 + row;
        cp_cg(sb + soff, A + (size_t)gr * 128 + c * 64 + u * 8, gr < ETOT ? 16 : 0);
    }
#pragma unroll
    for (int p = 0; p < 16; p++) {
        int i = tid + (p << 8);
        int c = i >> 11, j = i & 2047;
        int row = j >> 3, u = j & 7;
        uint32_t soff = 32768u + (uint32_t)c * 32768u + SMEM_SWZ((uint32_t)(row * 128 + u * 16));
        cp_cg(sb + soff, BT + (size_t)row * 128 + c * 64 + u * 8, 16);
    }
    CP_COMMIT();
    asm volatile("cp.async.wait_group 0;" ::: "memory");
    __syncthreads();

    float acc[4][8][4];
#pragma unroll
    for (int i = 0; i < 4; i++)
#pragma unroll
        for (int j = 0; j < 8; j++)
#pragma unroll
            for (int q = 0; q < 4; q++) acc[i][j][q] = 0.f;

#pragma unroll
    for (int c = 0; c < 2; c++) {
        uint32_t bA = sb + (uint32_t)c * 16384u;
        uint32_t bB = sb + 32768u + (uint32_t)c * 32768u;
#pragma unroll
        for (int ks = 0; ks < 4; ks++) {
            uint32_t a[4][4], b[8][2];
#pragma unroll
            for (int mi = 0; mi < 4; mi++) {
                uint32_t byte = (uint32_t)((wr * 64 + mi * 16 + (lane & 15)) * 128 +
                                           ks * 32 + ((lane >> 4) << 4));
                LDSM_X4(a[mi][0], a[mi][1], a[mi][2], a[mi][3], bA + SMEM_SWZ(byte));
            }
#pragma unroll
            for (int ni = 0; ni < 8; ni++) {
                uint32_t byte = (uint32_t)((wc * 64 + ni * 8 + (lane & 7)) * 128 +
                                           ks * 32 + (((lane >> 3) & 1) << 4));
                LDSM_X2(b[ni][0], b[ni][1], bB + SMEM_SWZ(byte));
            }
#pragma unroll
            for (int mi = 0; mi < 4; mi++)
#pragma unroll
                for (int ni = 0; ni < 8; ni++)
                    MMA16816(acc[mi][ni], a[mi][0], a[mi][1], a[mi][2], a[mi][3],
                             b[ni][0], b[ni][1]);
        }
    }

    // epilogue: score = sum_c att[c] * lrelu(ee + xl[s][c] + xr[d][c])
#pragma unroll
    for (int mi = 0; mi < 4; mi++) {
#pragma unroll
        for (int hf = 0; hf < 2; hf++) {
            int r = wr * 64 + mi * 16 + (lane >> 2) + hf * 8;
            int s = ss_s[r], d = sd_s[r];
            const float* xlp = g_xlr + (size_t)s * 512;
            const float* xrp = g_xlr + (size_t)d * 512 + 256;
            float h0 = 0.f, h1 = 0.f;
#pragma unroll
            for (int ni = 0; ni < 8; ni++) {
                int c0 = wc * 64 + ni * 8 + (lane & 3) * 2;
                float2 xlv = *(const float2*)(xlp + c0);
                float2 xrv = *(const float2*)(xrp + c0);
                float z0 = acc[mi][ni][hf * 2 + 0] + xlv.x + xrv.x;
                float z1 = acc[mi][ni][hf * 2 + 1] + xlv.y + xrv.y;
                z0 = (z0 > 0.f) ? z0 : 0.2f * z0;
                z1 = (z1 > 0.f) ? z1 : 0.2f * z1;
                float pp = z0 * att_s[c0] + z1 * att_s[c0 + 1];
                if (ni < 4) h0 += pp; else h1 += pp;
            }
            h0 += __shfl_xor_sync(0xffffffffu, h0, 1);
            h0 += __shfl_xor_sync(0xffffffffu, h0, 2);
            h1 += __shfl_xor_sync(0xffffffffu, h1, 1);
            h1 += __shfl_xor_sync(0xffffffffu, h1, 2);
            if ((lane & 3) == 0) {
                sc_s[r * 8 + wc * 2]     = h0;
                sc_s[r * 8 + wc * 2 + 1] = h1;
            }
        }
    }
    __syncthreads();
#pragma unroll
    for (int p = 0; p < 4; p++) {
        int i = tid + (p << 8);
        int r = i >> 3;
        int e = row0 + r;
        if (e < ETOT) g_sc[(size_t)e * 8 + (i & 7)] = sc_s[i];
    }
}

// ---------------- self-loop mean + CSR build ------------------------------------
__global__ void k_zero_loop() {
    int i = blockIdx.x * blockDim.x + threadIdx.x;
    if (i < Nn * EDIMc) g_loop[i] = 0.f;
    if (i < Nn)         g_cnt[i]  = 0.f;
}
__global__ void k_loop_accum(const int* __restrict__ dst, const float* __restrict__ ew) {
    int w    = (blockIdx.x * blockDim.x + threadIdx.x) >> 5;
    int lane = threadIdx.x & 31;
    if (w >= Ee) return;
    int d = dst[w];
    atomicAdd(&g_loop[d * EDIMc + lane], ew[(size_t)w * EDIMc + lane]);
    if (lane == 0) atomicAdd(&g_cnt[d], 1.f);
}
__global__ void k_loop_div() {
    int i = blockIdx.x * blockDim.x + threadIdx.x;
    if (i >= Nn * EDIMc) return;
    g_loop[i] /= fmaxf(g_cnt[i >> 5], 1.f);
}
__global__ void k_scan() {
    __shared__ int part[1024];
    int t = threadIdx.x;
    const int SEG = (Nn + 1023) / 1024;
    int base = t * SEG;
    int s = 0;
    for (int i = 0; i < SEG; i++) {
        int idx = base + i;
        if (idx < Nn) s += (int)g_cnt[idx];
    }
    part[t] = s;
    __syncthreads();
    for (int off = 1; off < 1024; off <<= 1) {
        int v = (t >= off) ? part[t - off] : 0;
        __syncthreads();
        part[t] += v;
        __syncthreads();
    }
    int run = (t == 0) ? 0 : part[t - 1];
    for (int i = 0; i < SEG; i++) {
        int idx = base + i;
        if (idx < Nn) {
            g_rowptr[idx] = run;
            g_tmp[idx] = run;
            run += (int)g_cnt[idx];
        }
    }
    if (t == 1023) g_rowptr[Nn] = run;
}
__global__ void k_scatter(const int* __restrict__ src, const int* __restrict__ dst) {
    int e = blockIdx.x * blockDim.x + threadIdx.x;
    if (e >= Ee) return;
    int pos = atomicAdd(&g_tmp[dst[e]], 1);
    g_adj[pos] = make_int2(src[e], e);
}

// ---------------- per-node fused softmax + aggregation ---------------------------
__global__ void k_node() {
    int d    = blockIdx.x * 8 + (threadIdx.x >> 5);
    int lane = threadIdx.x & 31;
    if (d >= Nn) return;
    int beg = g_rowptr[d], end = g_rowptr[d + 1];
    const float* ssc = g_sc + (size_t)(Ee + d) * Hh;

    float mx[Hh];
#pragma unroll
    for (int h = 0; h < Hh; h++) mx[h] = ssc[h];
    for (int i = beg + lane; i < end; i += 32) {
        const float* sc = g_sc + (size_t)g_adj[i].y * Hh;
#pragma unroll
        for (int h = 0; h < Hh; h++) mx[h] = fmaxf(mx[h], sc[h]);
    }
#pragma unroll
    for (int off = 16; off; off >>= 1)
#pragma unroll
        for (int h = 0; h < Hh; h++)
            mx[h] = fmaxf(mx[h], __shfl_xor_sync(0xffffffffu, mx[h], off));

    float dn[Hh];
#pragma unroll
    for (int h = 0; h < Hh; h++) dn[h] = 0.f;
    for (int i = beg + lane; i < end; i += 32) {
        const float* sc = g_sc + (size_t)g_adj[i].y * Hh;
#pragma unroll
        for (int h = 0; h < Hh; h++) dn[h] += __expf(sc[h] - mx[h]);
    }
#pragma unroll
    for (int off = 16; off; off >>= 1)
#pragma unroll
        for (int h = 0; h < Hh; h++)
            dn[h] += __shfl_xor_sync(0xffffffffu, dn[h], off);
#pragma unroll
    for (int h = 0; h < Hh; h++) dn[h] = 1.f / (dn[h] + __expf(ssc[h] - mx[h]));

    int hh = lane >> 2;
    int c0 = lane << 3;
    float m_h = mx[hh], inv_h = dn[hh];

    float acc[8];
    {
        float a = __expf(ssc[hh] - m_h) * inv_h;
        const float4* xp = (const float4*)(g_xlr + (size_t)d * 512 + c0);
        float4 u0 = xp[0], u1 = xp[1];
        acc[0] = a * u0.x; acc[1] = a * u0.y; acc[2] = a * u0.z; acc[3] = a * u0.w;
        acc[4] = a * u1.x; acc[5] = a * u1.y; acc[6] = a * u1.z; acc[7] = a * u1.w;
    }
    for (int i = beg; i < end; i++) {
        int2 se = g_adj[i];
        float a = __expf(g_sc[(size_t)se.y * Hh + hh] - m_h) * inv_h;
        const float4* xp = (const float4*)(g_xlr + (size_t)se.x * 512 + c0);
        float4 u0 = xp[0], u1 = xp[1];
        acc[0] += a * u0.x; acc[1] += a * u0.y; acc[2] += a * u0.z; acc[3] += a * u0.w;
        acc[4] += a * u1.x; acc[5] += a * u1.y; acc[6] += a * u1.z; acc[7] += a * u1.w;
    }
    float4* op = (float4*)(g_agg + (size_t)d * DIMc + c0);
    op[0] = make_float4(acc[0], acc[1], acc[2], acc[3]);
    op[1] = make_float4(acc[4], acc[5], acc[6], acc[7]);
}

// ---------------- BatchNorm -------------------------------------------------------
__global__ void k_zero_stats() {
    int t = threadIdx.x;
    if (t < DIMc) { g_sum[t] = 0.f; g_sumsq[t] = 0.f; }
}
__global__ void k_bnstats(const float* __restrict__ X) {
    int c = threadIdx.x;
    float s = 0.f, q = 0.f;
    for (int r = blockIdx.x; r < Nn; r += gridDim.x) {
        float v = X[(size_t)r * DIMc + c];
        s += v; q += v * v;
    }
    atomicAdd(&g_sum[c], s);
    atomicAdd(&g_sumsq[c], q);
}
template<bool PACK>
__global__ void k_bnapply(const float* __restrict__ X, const float* __restrict__ gam,
                          const float* __restrict__ bet, const float* __restrict__ res,
                          float* __restrict__ out) {
    int i = blockIdx.x * blockDim.x + threadIdx.x;
    if (i >= Nn * DIMc) return;
    int c = i & (DIMc - 1);
    float mu  = g_sum[c]   * (1.f / Nn);
    float var = g_sumsq[c] * (1.f / Nn) - mu * mu;
    float y = (X[i] - mu) * rsqrtf(var + 1e-5f) * gam[c] + bet[c];
    y = (y > 0.f) ? y : 0.01f * y;
    float v = res[i] + y;
    out[i] = v;
    if (PACK) {
        int r = i >> 8;
        __nv_bfloat16 h = __float2bfloat16(v);
        size_t b = (size_t)r * 768 + c;
        g_Apk[b]       = h;
        g_Apk[b + 256] = __float2bfloat16(v - __bfloat162float(h));
        g_Apk[b + 512] = h;
    }
}

// ---------------- host orchestration ----------------------------------------------
static inline int cdiv(int a, int b) { return (a + b - 1) / b; }

extern "C" void kernel_launch(void* const* d_in, const int* in_sizes, int n_in,
                              void* d_out, int out_size) {
    const float* nf    = (const float*)d_in[0];
    const int*   ei    = (const int*)  d_in[1];
    const float* ew    = (const float*)d_in[2];
    const float* g1_Wl = (const float*)d_in[3];
    const float* g1_Wr = (const float*)d_in[4];
    const float* g1_We = (const float*)d_in[5];
    const float* g1_at = (const float*)d_in[6];
    const float* g2_Wl = (const float*)d_in[8];
    const float* g2_Wr = (const float*)d_in[9];
    const float* g2_We = (const float*)d_in[10];
    const float* g2_at = (const float*)d_in[11];
    const float* n1_g  = (const float*)d_in[13];
    const float* n1_b  = (const float*)d_in[14];
    const float* n2_g  = (const float*)d_in[15];
    const float* n2_b  = (const float*)d_in[16];
    const float* n3_g  = (const float*)d_in[17];
    const float* n3_b  = (const float*)d_in[18];
    const float* ff_W1 = (const float*)d_in[19];
    const float* ff_b1 = (const float*)d_in[20];
    const float* ff_W2 = (const float*)d_in[21];
    const int* src = ei;
    const int* dst = ei + Ee;
    float* out = (float*)d_out;

    void* p;
    cudaGetSymbolAddress(&p, g_xlr);  float* xlr  = (float*)p;
    cudaGetSymbolAddress(&p, g_agg);  float* agg  = (float*)p;
    cudaGetSymbolAddress(&p, g_h1);   float* h1   = (float*)p;
    cudaGetSymbolAddress(&p, g_h2);   float* h2   = (float*)p;
    cudaGetSymbolAddress(&p, g_ff2);  float* ff2  = (float*)p;
    cudaGetSymbolAddress(&p, g_Apk);  __nv_bfloat16* Apk = (__nv_bfloat16*)p;
    cudaGetSymbolAddress(&p, g_Fpk);  __nv_bfloat16* Fpk = (__nv_bfloat16*)p;
    cudaGetSymbolAddress(&p, g_EApk); __nv_bfloat16* EApk = (__nv_bfloat16*)p;
    cudaGetSymbolAddress(&p, g_Wpk);  __nv_bfloat16* Wpk = (__nv_bfloat16*)p;

    cudaFuncSetAttribute(gemm_pk<0>, cudaFuncAttributeMaxDynamicSharedMemorySize, GEMM_SMEM_PK);
    cudaFuncSetAttribute(gemm_pk<1>, cudaFuncAttributeMaxDynamicSharedMemorySize, GEMM_SMEM_PK);
    cudaFuncSetAttribute(gemm_score, cudaFuncAttributeMaxDynamicSharedMemorySize, SC_SMEM);

    // ---- weight packs ----
    k_packT_w<<<cdiv(DIMc * DIMc, 256), 256>>>(g1_Wl, Wpk + OWLR1, DIMc, DIMc, 768);
    k_packT_w<<<cdiv(DIMc * DIMc, 256), 256>>>(g1_Wr, Wpk + OWLR1 + 256 * 768, DIMc, DIMc, 768);
    k_packT_w<<<cdiv(EDIMc * DIMc, 256), 256>>>(g1_We, Wpk + OWE1, EDIMc, DIMc, 128);
    k_packT_w<<<cdiv(DIMc * DIMc, 256), 256>>>(g2_Wl, Wpk + OWLR2, DIMc, DIMc, 768);
    k_packT_w<<<cdiv(DIMc * DIMc, 256), 256>>>(g2_Wr, Wpk + OWLR2 + 256 * 768, DIMc, DIMc, 768);
    k_packT_w<<<cdiv(EDIMc * DIMc, 256), 256>>>(g2_We, Wpk + OWE2, EDIMc, DIMc, 128);
    k_packT_w<<<cdiv(DIMc * DFFc, 256), 256>>>(ff_W1, Wpk + OW1, DIMc, DFFc, 768);
    k_packT_w<<<cdiv(DFFc * DIMc, 256), 256>>>(ff_W2, Wpk + OW2, DFFc, DIMc, 3072);

    // ---- self-loop edge features + CSR (once) ----
    k_zero_loop<<<cdiv(Nn * EDIMc, 256), 256>>>();
    k_loop_accum<<<cdiv(Ee * 32, 256), 256>>>(dst, ew);
    k_loop_div<<<cdiv(Nn * EDIMc, 256), 256>>>();
    k_scan<<<1, 1024>>>();
    k_scatter<<<cdiv(Ee, 256), 256>>>(src, dst);
    k_pack_ea<<<cdiv(ETOT * EDIMc, 256), 256>>>(ew);

    dim3 gXLR(4, cdiv(Nn, 128));
    int nbScore = cdiv(ETOT, 128);
    int nbNode  = cdiv(Nn, 8);

    // ---- block 1 ----
    k_pack_node<<<cdiv(Nn * DIMc, 256), 256>>>(nf, Apk, Nn, DIMc);
    gemm_pk<0><<<gXLR, 256, GEMM_SMEM_PK>>>(Apk, Wpk + OWLR1, nullptr, xlr, Nn, 768, 512);
    gemm_score<<<nbScore, 256, SC_SMEM>>>(EApk, Wpk + OWE1, g1_at, src, dst);
    k_node<<<nbNode, 256>>>();
    k_zero_stats<<<1, 256>>>();
    k_bnstats<<<256, 256>>>(agg);
    k_bnapply<true><<<cdiv(Nn * DIMc, 256), 256>>>(agg, n1_g, n1_b, nf, h1);

    // ---- block 2 ----
    gemm_pk<0><<<gXLR, 256, GEMM_SMEM_PK>>>(Apk, Wpk + OWLR2, nullptr, xlr, Nn, 768, 512);
    gemm_score<<<nbScore, 256, SC_SMEM>>>(EApk, Wpk + OWE2, g2_at, src, dst);
    k_node<<<nbNode, 256>>>();
    k_zero_stats<<<1, 256>>>();
    k_bnstats<<<256, 256>>>(agg);
    k_bnapply<true><<<cdiv(Nn * DIMc, 256), 256>>>(agg, n2_g, n2_b, h1, h2);

    // ---- feed-forward ----
    dim3 gF1(8, cdiv(Nn, 128));
    gemm_pk<1><<<gF1, 256, GEMM_SMEM_PK>>>(Apk, Wpk + OW1, ff_b1, nullptr, Nn, 768, DFFc);
    dim3 gF2(2, cdiv(Nn, 128));
    gemm_pk<0><<<gF2, 256, GEMM_SMEM_PK>>>(Fpk, Wpk + OW2, nullptr, ff2, Nn, 3072, DIMc);
    k_zero_stats<<<1, 256>>>();
    k_bnstats<<<256, 256>>>(ff2);
    k_bnapply<false><<<cdiv(Nn * DIMc, 256), 256>>>(ff2, n3_g, n3_b, h2, out);
}

// round 7
// speedup vs baseline: 1.8790x; 1.0215x over previous
#include <cuda_runtime.h>
#include <cuda_bf16.h>
#include <cuda_fp16.h>
#include <math.h>
#include <stdint.h>

#define Nn    20000
#define Ee    320000
#define DIMc  256
#define Hh    8
#define EDIMc 32
#define DFFc  1024
#define ETOT  (Ee + Nn)

// ---------------- scratch (device globals) -----------------------------------
static __device__ float    g_xlr[(size_t)Nn * 512];        // [xl | xr] fp32
static __device__ __half   g_xlrh[(size_t)Nn * 512];       // fp16 shadow (score only)
static __device__ float    g_loop[(size_t)Nn * EDIMc];
static __device__ float    g_cnt[Nn];
static __device__ float    g_sc [(size_t)ETOT * Hh];
static __device__ float    g_agg[(size_t)Nn * DIMc];
static __device__ float    g_h1 [(size_t)Nn * DIMc];
static __device__ float    g_h2 [(size_t)Nn * DIMc];
static __device__ float    g_ff2[(size_t)Nn * DIMc];
static __device__ float    g_sum[DIMc];
static __device__ float    g_sumsq[DIMc];
// CSR
static __device__ int      g_rowptr[Nn + 1];
static __device__ int      g_tmp[Nn];
static __device__ int2     g_adj[Ee];

// packed bf16 operands
static __device__ __nv_bfloat16 g_Apk[(size_t)Nn * 768];
static __device__ __nv_bfloat16 g_Fpk[(size_t)Nn * 3072];
static __device__ __nv_bfloat16 g_EApk[(size_t)ETOT * 128];
#define OWLR1 0
#define OWE1  393216
#define OWLR2 425984
#define OWE2  819200
#define OW1   851968
#define OW2   1638400
#define WPK_TOTAL 2424832
static __device__ __nv_bfloat16 g_Wpk[WPK_TOTAL];

// ---------------- PTX helpers --------------------------------------------------
__device__ __forceinline__ uint32_t smem_u32(const void* p) {
    uint32_t a;
    asm("{ .reg .u64 t; cvta.to.shared.u64 t, %1; cvt.u32.u64 %0, t; }"
        : "=r"(a) : "l"(p));
    return a;
}
#define LDSM_X4(r0, r1, r2, r3, addr) \
    asm volatile("ldmatrix.sync.aligned.m8n8.x4.shared.b16 {%0,%1,%2,%3}, [%4];" \
                 : "=r"(r0), "=r"(r1), "=r"(r2), "=r"(r3) : "r"(addr))
#define LDSM_X2(r0, r1, addr) \
    asm volatile("ldmatrix.sync.aligned.m8n8.x2.shared.b16 {%0,%1}, [%2];" \
                 : "=r"(r0), "=r"(r1) : "r"(addr))
#define MMA16816(c, a0, a1, a2, a3, b0, b1) \
    asm volatile("mma.sync.aligned.m16n8k16.row.col.f32.bf16.bf16.f32 " \
                 "{%0,%1,%2,%3}, {%4,%5,%6,%7}, {%8,%9}, {%0,%1,%2,%3};" \
                 : "+f"((c)[0]), "+f"((c)[1]), "+f"((c)[2]), "+f"((c)[3]) \
                 : "r"(a0), "r"(a1), "r"(a2), "r"(a3), "r"(b0), "r"(b1))
__device__ __forceinline__ void cp_cg(uint32_t dst, const void* src, int sz) {
    asm volatile("cp.async.cg.shared.global [%0], [%1], 16, %2;"
                 :: "r"(dst), "l"(src), "r"(sz));
}
#define CP_COMMIT() asm volatile("cp.async.commit_group;" ::: "memory")
#define SMEM_SWZ(b) ((b) ^ (((b) >> 3) & 0x70))

// ---------------- pack kernels --------------------------------------------------
__global__ void k_pack_node(const float* __restrict__ X, __nv_bfloat16* __restrict__ A,
                            int rows, int K) {
    int i = blockIdx.x * blockDim.x + threadIdx.x;
    if (i >= rows * K) return;
    int r = i / K, k = i - r * K;
    float v = X[i];
    __nv_bfloat16 h = __float2bfloat16(v);
    __nv_bfloat16 l = __float2bfloat16(v - __bfloat162float(h));
    size_t b = (size_t)r * (3 * K);
    A[b + k] = h;
    A[b + K + k] = l;
    A[b + 2 * K + k] = h;
}
__global__ void k_pack_ea(const float* __restrict__ ew) {
    int i = blockIdx.x * blockDim.x + threadIdx.x;
    if (i >= ETOT * EDIMc) return;
    int r = i >> 5, k = i & 31;
    float v = (r < Ee) ? ew[i] : g_loop[(size_t)(r - Ee) * EDIMc + k];
    __nv_bfloat16 h = __float2bfloat16(v);
    __nv_bfloat16 l = __float2bfloat16(v - __bfloat162float(h));
    size_t b = (size_t)r * 128;
    g_EApk[b + k]      = h;
    g_EApk[b + 32 + k] = l;
    g_EApk[b + 64 + k] = h;
    g_EApk[b + 96 + k] = __float2bfloat16(0.f);
}
__global__ void k_packT_w(const float* __restrict__ W, __nv_bfloat16* __restrict__ WT,
                          int K, int N, int Kp) {
    int i = blockIdx.x * blockDim.x + threadIdx.x;
    if (i >= K * N) return;
    int k = i / N, n = i - k * N;
    float v = W[i];
    __nv_bfloat16 h = __float2bfloat16(v);
    __nv_bfloat16 l = __float2bfloat16(v - __bfloat162float(h));
    size_t b = (size_t)n * Kp;
    WT[b + k]         = h;
    WT[b + K + k]     = h;
    WT[b + 2 * K + k] = l;
    if (k < Kp - 3 * K) WT[b + 3 * K + k] = __float2bfloat16(0.f);
}

// ---------------- pipelined bf16 GEMM (K-packed x3) ----------------------------
// EPI: 0 = fp32 out; 1 = relu+bias -> [hi|lo|hi] pack in g_Fpk; 2 = fp32 + fp16 shadow
#define GEMM_SMEM_PK 65536

template<int EPI>
__global__ void __launch_bounds__(256, 2) gemm_pk(
    const __nv_bfloat16* __restrict__ A, const __nv_bfloat16* __restrict__ BT,
    const float* __restrict__ bias, float* __restrict__ C,
    int M, int Kp, int Nc) {
    extern __shared__ __nv_bfloat16 sm[];
    uint32_t sb = smem_u32(sm);
    int tid  = threadIdx.x;
    int lane = tid & 31;
    int w    = tid >> 5;
    int wr   = w & 1;
    int wc   = w >> 1;
    int row0 = blockIdx.y * 128;
    int col0 = blockIdx.x * 128;

    float acc[4][4][4];
#pragma unroll
    for (int i = 0; i < 4; i++)
#pragma unroll
        for (int j = 0; j < 4; j++)
#pragma unroll
            for (int q = 0; q < 4; q++) acc[i][j][q] = 0.f;

    const int nch = Kp >> 6;

    auto issue = [&](int c, int stage) {
        uint32_t sA = sb + (uint32_t)stage * 32768u;
        uint32_t sB = sA + 16384u;
        int k0 = c << 6;
#pragma unroll
        for (int p = 0; p < 4; p++) {
            int idx = tid + (p << 8);
            int row = idx >> 3, u = idx & 7;
            uint32_t soff = SMEM_SWZ((uint32_t)(row * 128 + u * 16));
            int gr = row0 + row;
            cp_cg(sA + soff, A + (size_t)gr * Kp + k0 + u * 8, gr < M ? 16 : 0);
            cp_cg(sB + soff, BT + (size_t)(col0 + row) * Kp + k0 + u * 8, 16);
        }
        CP_COMMIT();
    };
    auto compute = [&](int stage) {
        uint32_t bA = sb + (uint32_t)stage * 32768u;
        uint32_t bB = bA + 16384u;
#pragma unroll
        for (int ks = 0; ks < 4; ks++) {
            uint32_t a[4][4], b[4][2];
#pragma unroll
            for (int mi = 0; mi < 4; mi++) {
                uint32_t byte = (uint32_t)((wr * 64 + mi * 16 + (lane & 15)) * 128 +
                                           ks * 32 + ((lane >> 4) << 4));
                LDSM_X4(a[mi][0], a[mi][1], a[mi][2], a[mi][3], bA + SMEM_SWZ(byte));
            }
#pragma unroll
            for (int ni = 0; ni < 4; ni++) {
                uint32_t byte = (uint32_t)((wc * 32 + ni * 8 + (lane & 7)) * 128 +
                                           ks * 32 + (((lane >> 3) & 1) << 4));
                LDSM_X2(b[ni][0], b[ni][1], bB + SMEM_SWZ(byte));
            }
#pragma unroll
            for (int mi = 0; mi < 4; mi++)
#pragma unroll
                for (int ni = 0; ni < 4; ni++)
                    MMA16816(acc[mi][ni], a[mi][0], a[mi][1], a[mi][2], a[mi][3],
                             b[ni][0], b[ni][1]);
        }
    };

    issue(0, 0);
    for (int c = 0; c < nch; c++) {
        if (c + 1 < nch) {
            issue(c + 1, (c + 1) & 1);
            asm volatile("cp.async.wait_group 1;" ::: "memory");
        } else {
            asm volatile("cp.async.wait_group 0;" ::: "memory");
        }
        __syncthreads();
        compute(c & 1);
        __syncthreads();
    }

#pragma unroll
    for (int mi = 0; mi < 4; mi++) {
#pragma unroll
        for (int ni = 0; ni < 4; ni++) {
            int r = row0 + wr * 64 + mi * 16 + (lane >> 2);
            int c = col0 + wc * 32 + ni * 8 + (lane & 3) * 2;
            float v0 = acc[mi][ni][0], v1 = acc[mi][ni][1];
            float v2 = acc[mi][ni][2], v3 = acc[mi][ni][3];
            if (EPI == 1) {
                float b0 = bias[c], b1 = bias[c + 1];
                v0 = fmaxf(v0 + b0, 0.f); v1 = fmaxf(v1 + b1, 0.f);
                v2 = fmaxf(v2 + b0, 0.f); v3 = fmaxf(v3 + b1, 0.f);
                __nv_bfloat16* P = g_Fpk;
#pragma unroll
                for (int hh = 0; hh < 2; hh++) {
                    int rr = r + hh * 8;
                    if (rr >= M) continue;
                    float u0 = hh ? v2 : v0, u1 = hh ? v3 : v1;
                    size_t base = (size_t)rr * 3072 + c;
                    __nv_bfloat16 h0 = __float2bfloat16(u0);
                    __nv_bfloat16 h1 = __float2bfloat16(u1);
                    P[base]          = h0;
                    P[base + 1]      = h1;
                    P[base + 1024]   = __float2bfloat16(u0 - __bfloat162float(h0));
                    P[base + 1025]   = __float2bfloat16(u1 - __bfloat162float(h1));
                    P[base + 2048]   = h0;
                    P[base + 2049]   = h1;
                }
            } else {
                if (r < M) {
                    C[(size_t)r * Nc + c] = v0;
                    C[(size_t)r * Nc + c + 1] = v1;
                    if (EPI == 2)
                        *(__half2*)(g_xlrh + (size_t)r * 512 + c) = __floats2half2_rn(v0, v1);
                }
                if (r + 8 < M) {
                    C[(size_t)(r + 8) * Nc + c] = v2;
                    C[(size_t)(r + 8) * Nc + c + 1] = v3;
                    if (EPI == 2)
                        *(__half2*)(g_xlrh + (size_t)(r + 8) * 512 + c) = __floats2half2_rn(v2, v3);
                }
            }
        }
    }
}

// ---------------- ee GEMM fused with GATv2 score --------------------------------
#define SC_SMEM 104448

__global__ void __launch_bounds__(256, 1) gemm_score(
    const __nv_bfloat16* __restrict__ A, const __nv_bfloat16* __restrict__ BT,
    const float* __restrict__ att,
    const int* __restrict__ src, const int* __restrict__ dst) {
    extern __shared__ char smc[];
    uint32_t sb = smem_u32(smc);
    float* sc_s  = (float*)(smc + 98304);
    float* att_s = (float*)(smc + 102400);
    int*   ss_s  = (int*)(smc + 103424);
    int*   sd_s  = (int*)(smc + 103936);
    int tid = threadIdx.x, lane = tid & 31, w = tid >> 5;
    int wr = w & 1, wc = w >> 1;
    int row0 = blockIdx.x * 128;

    att_s[tid] = att[tid];
    if (tid < 128) {
        int e = row0 + tid;
        int s, d;
        if (e < Ee)       { s = src[e]; d = dst[e]; }
        else if (e < ETOT){ s = e - Ee; d = s; }
        else              { s = 0; d = 0; }
        ss_s[tid] = s; sd_s[tid] = d;
    }
#pragma unroll
    for (int p = 0; p < 8; p++) {
        int i = tid + (p << 8);
        int c = i >> 10, j = i & 1023;
        int row = j >> 3, u = j & 7;
        uint32_t soff = (uint32_t)c * 16384u + SMEM_SWZ((uint32_t)(row * 128 + u * 16));
        int gr = row0 + row;
        cp_cg(sb + soff, A + (size_t)gr * 128 + c * 64 + u * 8, gr < ETOT ? 16 : 0);
    }
#pragma unroll
    for (int p = 0; p < 16; p++) {
        int i = tid + (p << 8);
        int c = i >> 11, j = i & 2047;
        int row = j >> 3, u = j & 7;
        uint32_t soff = 32768u + (uint32_t)c * 32768u + SMEM_SWZ((uint32_t)(row * 128 + u * 16));
        cp_cg(sb + soff, BT + (size_t)row * 128 + c * 64 + u * 8, 16);
    }
    CP_COMMIT();
    asm volatile("cp.async.wait_group 0;" ::: "memory");
    __syncthreads();

    float acc[4][8][4];
#pragma unroll
    for (int i = 0; i < 4; i++)
#pragma unroll
        for (int j = 0; j < 8; j++)
#pragma unroll
            for (int q = 0; q < 4; q++) acc[i][j][q] = 0.f;

#pragma unroll
    for (int c = 0; c < 2; c++) {
        uint32_t bA = sb + (uint32_t)c * 16384u;
        uint32_t bB = sb + 32768u + (uint32_t)c * 32768u;
#pragma unroll
        for (int ks = 0; ks < 4; ks++) {
            uint32_t a[4][4], b[8][2];
#pragma unroll
            for (int mi = 0; mi < 4; mi++) {
                uint32_t byte = (uint32_t)((wr * 64 + mi * 16 + (lane & 15)) * 128 +
                                           ks * 32 + ((lane >> 4) << 4));
                LDSM_X4(a[mi][0], a[mi][1], a[mi][2], a[mi][3], bA + SMEM_SWZ(byte));
            }
#pragma unroll
            for (int ni = 0; ni < 8; ni++) {
                uint32_t byte = (uint32_t)((wc * 64 + ni * 8 + (lane & 7)) * 128 +
                                           ks * 32 + (((lane >> 3) & 1) << 4));
                LDSM_X2(b[ni][0], b[ni][1], bB + SMEM_SWZ(byte));
            }
#pragma unroll
            for (int mi = 0; mi < 4; mi++)
#pragma unroll
                for (int ni = 0; ni < 8; ni++)
                    MMA16816(acc[mi][ni], a[mi][0], a[mi][1], a[mi][2], a[mi][3],
                             b[ni][0], b[ni][1]);
        }
    }

    // epilogue: score = sum_c att[c] * lrelu(ee + xl[s][c] + xr[d][c])  (fp16 gather)
#pragma unroll
    for (int mi = 0; mi < 4; mi++) {
#pragma unroll
        for (int hf = 0; hf < 2; hf++) {
            int r = wr * 64 + mi * 16 + (lane >> 2) + hf * 8;
            int s = ss_s[r], d = sd_s[r];
            const __half* xlp = g_xlrh + (size_t)s * 512;
            const __half* xrp = g_xlrh + (size_t)d * 512 + 256;
            float h0 = 0.f, h1 = 0.f;
#pragma unroll
            for (int ni = 0; ni < 8; ni++) {
                int c0 = wc * 64 + ni * 8 + (lane & 3) * 2;
                float2 xlv = __half22float2(*(const __half2*)(xlp + c0));
                float2 xrv = __half22float2(*(const __half2*)(xrp + c0));
                float z0 = acc[mi][ni][hf * 2 + 0] + xlv.x + xrv.x;
                float z1 = acc[mi][ni][hf * 2 + 1] + xlv.y + xrv.y;
                z0 = (z0 > 0.f) ? z0 : 0.2f * z0;
                z1 = (z1 > 0.f) ? z1 : 0.2f * z1;
                float pp = z0 * att_s[c0] + z1 * att_s[c0 + 1];
                if (ni < 4) h0 += pp; else h1 += pp;
            }
            h0 += __shfl_xor_sync(0xffffffffu, h0, 1);
            h0 += __shfl_xor_sync(0xffffffffu, h0, 2);
            h1 += __shfl_xor_sync(0xffffffffu, h1, 1);
            h1 += __shfl_xor_sync(0xffffffffu, h1, 2);
            if ((lane & 3) == 0) {
                sc_s[r * 8 + wc * 2]     = h0;
                sc_s[r * 8 + wc * 2 + 1] = h1;
            }
        }
    }
    __syncthreads();
#pragma unroll
    for (int p = 0; p < 4; p++) {
        int i = tid + (p << 8);
        int r = i >> 3;
        int e = row0 + r;
        if (e < ETOT) g_sc[(size_t)e * 8 + (i & 7)] = sc_s[i];
    }
}

// ---------------- self-loop mean + CSR build ------------------------------------
__global__ void k_zero_loop() {
    int i = blockIdx.x * blockDim.x + threadIdx.x;
    if (i < Nn * EDIMc) g_loop[i] = 0.f;
    if (i < Nn)         g_cnt[i]  = 0.f;
}
__global__ void k_loop_accum(const int* __restrict__ dst, const float* __restrict__ ew) {
    int w    = (blockIdx.x * blockDim.x + threadIdx.x) >> 5;
    int lane = threadIdx.x & 31;
    if (w >= Ee) return;
    int d = dst[w];
    atomicAdd(&g_loop[d * EDIMc + lane], ew[(size_t)w * EDIMc + lane]);
    if (lane == 0) atomicAdd(&g_cnt[d], 1.f);
}
__global__ void k_loop_div() {
    int i = blockIdx.x * blockDim.x + threadIdx.x;
    if (i >= Nn * EDIMc) return;
    g_loop[i] /= fmaxf(g_cnt[i >> 5], 1.f);
}
__global__ void k_scan() {
    __shared__ int part[1024];
    int t = threadIdx.x;
    const int SEG = (Nn + 1023) / 1024;
    int base = t * SEG;
    int s = 0;
    for (int i = 0; i < SEG; i++) {
        int idx = base + i;
        if (idx < Nn) s += (int)g_cnt[idx];
    }
    part[t] = s;
    __syncthreads();
    for (int off = 1; off < 1024; off <<= 1) {
        int v = (t >= off) ? part[t - off] : 0;
        __syncthreads();
        part[t] += v;
        __syncthreads();
    }
    int run = (t == 0) ? 0 : part[t - 1];
    for (int i = 0; i < SEG; i++) {
        int idx = base + i;
        if (idx < Nn) {
            g_rowptr[idx] = run;
            g_tmp[idx] = run;
            run += (int)g_cnt[idx];
        }
    }
    if (t == 1023) g_rowptr[Nn] = run;
}
__global__ void k_scatter(const int* __restrict__ src, const int* __restrict__ dst) {
    int e = blockIdx.x * blockDim.x + threadIdx.x;
    if (e >= Ee) return;
    int pos = atomicAdd(&g_tmp[dst[e]], 1);
    g_adj[pos] = make_int2(src[e], e);
}

// ---------------- per-node fused softmax + aggregation (2-pass) ------------------
__global__ void k_node() {
    int d    = blockIdx.x * 8 + (threadIdx.x >> 5);
    int lane = threadIdx.x & 31;
    if (d >= Nn) return;
    int beg = g_rowptr[d], end = g_rowptr[d + 1];
    const float* ssc = g_sc + (size_t)(Ee + d) * Hh;

    // pass 1: per-head max (strided + shuffle)
    float mx[Hh];
#pragma unroll
    for (int h = 0; h < Hh; h++) mx[h] = ssc[h];
    for (int i = beg + lane; i < end; i += 32) {
        const float* sc = g_sc + (size_t)g_adj[i].y * Hh;
#pragma unroll
        for (int h = 0; h < Hh; h++) mx[h] = fmaxf(mx[h], sc[h]);
    }
#pragma unroll
    for (int off = 16; off; off >>= 1)
#pragma unroll
        for (int h = 0; h < Hh; h++)
            mx[h] = fmaxf(mx[h], __shfl_xor_sync(0xffffffffu, mx[h], off));

    // pass 2: fused denominator + weighted aggregation (serial over all edges;
    // each lane independently accumulates the complete den for its head)
    int hh = lane >> 2;
    int c0 = lane << 3;
    float m_h = mx[hh];

    float den;
    float acc[8];
    {
        float a = __expf(ssc[hh] - m_h);
        den = a;
        const float4* xp = (const float4*)(g_xlr + (size_t)d * 512 + c0);
        float4 u0 = xp[0], u1 = xp[1];
        acc[0] = a * u0.x; acc[1] = a * u0.y; acc[2] = a * u0.z; acc[3] = a * u0.w;
        acc[4] = a * u1.x; acc[5] = a * u1.y; acc[6] = a * u1.z; acc[7] = a * u1.w;
    }
    for (int i = beg; i < end; i++) {
        int2 se = g_adj[i];
        float a = __expf(g_sc[(size_t)se.y * Hh + hh] - m_h);
        den += a;
        const float4* xp = (const float4*)(g_xlr + (size_t)se.x * 512 + c0);
        float4 u0 = xp[0], u1 = xp[1];
        acc[0] += a * u0.x; acc[1] += a * u0.y; acc[2] += a * u0.z; acc[3] += a * u0.w;
        acc[4] += a * u1.x; acc[5] += a * u1.y; acc[6] += a * u1.z; acc[7] += a * u1.w;
    }
    float inv = 1.f / den;
#pragma unroll
    for (int q = 0; q < 8; q++) acc[q] *= inv;

    float4* op = (float4*)(g_agg + (size_t)d * DIMc + c0);
    op[0] = make_float4(acc[0], acc[1], acc[2], acc[3]);
    op[1] = make_float4(acc[4], acc[5], acc[6], acc[7]);
}

// ---------------- BatchNorm -------------------------------------------------------
__global__ void k_zero_stats() {
    int t = threadIdx.x;
    if (t < DIMc) { g_sum[t] = 0.f; g_sumsq[t] = 0.f; }
}
__global__ void k_bnstats(const float* __restrict__ X) {
    int c = threadIdx.x;
    float s = 0.f, q = 0.f;
    for (int r = blockIdx.x; r < Nn; r += gridDim.x) {
        float v = X[(size_t)r * DIMc + c];
        s += v; q += v * v;
    }
    atomicAdd(&g_sum[c], s);
    atomicAdd(&g_sumsq[c], q);
}
template<bool PACK>
__global__ void k_bnapply(const float* __restrict__ X, const float* __restrict__ gam,
                          const float* __restrict__ bet, const float* __restrict__ res,
                          float* __restrict__ out) {
    int i = blockIdx.x * blockDim.x + threadIdx.x;
    if (i >= Nn * DIMc) return;
    int c = i & (DIMc - 1);
    float mu  = g_sum[c]   * (1.f / Nn);
    float var = g_sumsq[c] * (1.f / Nn) - mu * mu;
    float y = (X[i] - mu) * rsqrtf(var + 1e-5f) * gam[c] + bet[c];
    y = (y > 0.f) ? y : 0.01f * y;
    float v = res[i] + y;
    out[i] = v;
    if (PACK) {
        int r = i >> 8;
        __nv_bfloat16 h = __float2bfloat16(v);
        size_t b = (size_t)r * 768 + c;
        g_Apk[b]       = h;
        g_Apk[b + 256] = __float2bfloat16(v - __bfloat162float(h));
        g_Apk[b + 512] = h;
    }
}

// ---------------- host orchestration ----------------------------------------------
static inline int cdiv(int a, int b) { return (a + b - 1) / b; }

extern "C" void kernel_launch(void* const* d_in, const int* in_sizes, int n_in,
                              void* d_out, int out_size) {
    const float* nf    = (const float*)d_in[0];
    const int*   ei    = (const int*)  d_in[1];
    const float* ew    = (const float*)d_in[2];
    const float* g1_Wl = (const float*)d_in[3];
    const float* g1_Wr = (const float*)d_in[4];
    const float* g1_We = (const float*)d_in[5];
    const float* g1_at = (const float*)d_in[6];
    const float* g2_Wl = (const float*)d_in[8];
    const float* g2_Wr = (const float*)d_in[9];
    const float* g2_We = (const float*)d_in[10];
    const float* g2_at = (const float*)d_in[11];
    const float* n1_g  = (const float*)d_in[13];
    const float* n1_b  = (const float*)d_in[14];
    const float* n2_g  = (const float*)d_in[15];
    const float* n2_b  = (const float*)d_in[16];
    const float* n3_g  = (const float*)d_in[17];
    const float* n3_b  = (const float*)d_in[18];
    const float* ff_W1 = (const float*)d_in[19];
    const float* ff_b1 = (const float*)d_in[20];
    const float* ff_W2 = (const float*)d_in[21];
    const int* src = ei;
    const int* dst = ei + Ee;
    float* out = (float*)d_out;

    void* p;
    cudaGetSymbolAddress(&p, g_xlr);  float* xlr  = (float*)p;
    cudaGetSymbolAddress(&p, g_agg);  float* agg  = (float*)p;
    cudaGetSymbolAddress(&p, g_h1);   float* h1   = (float*)p;
    cudaGetSymbolAddress(&p, g_h2);   float* h2   = (float*)p;
    cudaGetSymbolAddress(&p, g_ff2);  float* ff2  = (float*)p;
    cudaGetSymbolAddress(&p, g_Apk);  __nv_bfloat16* Apk = (__nv_bfloat16*)p;
    cudaGetSymbolAddress(&p, g_Fpk);  __nv_bfloat16* Fpk = (__nv_bfloat16*)p;
    cudaGetSymbolAddress(&p, g_EApk); __nv_bfloat16* EApk = (__nv_bfloat16*)p;
    cudaGetSymbolAddress(&p, g_Wpk);  __nv_bfloat16* Wpk = (__nv_bfloat16*)p;

    cudaFuncSetAttribute(gemm_pk<0>, cudaFuncAttributeMaxDynamicSharedMemorySize, GEMM_SMEM_PK);
    cudaFuncSetAttribute(gemm_pk<1>, cudaFuncAttributeMaxDynamicSharedMemorySize, GEMM_SMEM_PK);
    cudaFuncSetAttribute(gemm_pk<2>, cudaFuncAttributeMaxDynamicSharedMemorySize, GEMM_SMEM_PK);
    cudaFuncSetAttribute(gemm_score, cudaFuncAttributeMaxDynamicSharedMemorySize, SC_SMEM);

    // ---- weight packs ----
    k_packT_w<<<cdiv(DIMc * DIMc, 256), 256>>>(g1_Wl, Wpk + OWLR1, DIMc, DIMc, 768);
    k_packT_w<<<cdiv(DIMc * DIMc, 256), 256>>>(g1_Wr, Wpk + OWLR1 + 256 * 768, DIMc, DIMc, 768);
    k_packT_w<<<cdiv(EDIMc * DIMc, 256), 256>>>(g1_We, Wpk + OWE1, EDIMc, DIMc, 128);
    k_packT_w<<<cdiv(DIMc * DIMc, 256), 256>>>(g2_Wl, Wpk + OWLR2, DIMc, DIMc, 768);
    k_packT_w<<<cdiv(DIMc * DIMc, 256), 256>>>(g2_Wr, Wpk + OWLR2 + 256 * 768, DIMc, DIMc, 768);
    k_packT_w<<<cdiv(EDIMc * DIMc, 256), 256>>>(g2_We, Wpk + OWE2, EDIMc, DIMc, 128);
    k_packT_w<<<cdiv(DIMc * DFFc, 256), 256>>>(ff_W1, Wpk + OW1, DIMc, DFFc, 768);
    k_packT_w<<<cdiv(DFFc * DIMc, 256), 256>>>(ff_W2, Wpk + OW2, DFFc, DIMc, 3072);

    // ---- self-loop edge features + CSR (once) ----
    k_zero_loop<<<cdiv(Nn * EDIMc, 256), 256>>>();
    k_loop_accum<<<cdiv(Ee * 32, 256), 256>>>(dst, ew);
    k_loop_div<<<cdiv(Nn * EDIMc, 256), 256>>>();
    k_scan<<<1, 1024>>>();
    k_scatter<<<cdiv(Ee, 256), 256>>>(src, dst);
    k_pack_ea<<<cdiv(ETOT * EDIMc, 256), 256>>>(ew);

    dim3 gXLR(4, cdiv(Nn, 128));
    int nbScore = cdiv(ETOT, 128);
    int nbNode  = cdiv(Nn, 8);

    // ---- block 1 ----
    k_pack_node<<<cdiv(Nn * DIMc, 256), 256>>>(nf, Apk, Nn, DIMc);
    gemm_pk<2><<<gXLR, 256, GEMM_SMEM_PK>>>(Apk, Wpk + OWLR1, nullptr, xlr, Nn, 768, 512);
    gemm_score<<<nbScore, 256, SC_SMEM>>>(EApk, Wpk + OWE1, g1_at, src, dst);
    k_node<<<nbNode, 256>>>();
    k_zero_stats<<<1, 256>>>();
    k_bnstats<<<256, 256>>>(agg);
    k_bnapply<true><<<cdiv(Nn * DIMc, 256), 256>>>(agg, n1_g, n1_b, nf, h1);

    // ---- block 2 ----
    gemm_pk<2><<<gXLR, 256, GEMM_SMEM_PK>>>(Apk, Wpk + OWLR2, nullptr, xlr, Nn, 768, 512);
    gemm_score<<<nbScore, 256, SC_SMEM>>>(EApk, Wpk + OWE2, g2_at, src, dst);
    k_node<<<nbNode, 256>>>();
    k_zero_stats<<<1, 256>>>();
    k_bnstats<<<256, 256>>>(agg);
    k_bnapply<true><<<cdiv(Nn * DIMc, 256), 256>>>(agg, n2_g, n2_b, h1, h2);

    // ---- feed-forward ----
    dim3 gF1(8, cdiv(Nn, 128));
    gemm_pk<1><<<gF1, 256, GEMM_SMEM_PK>>>(Apk, Wpk + OW1, ff_b1, nullptr, Nn, 768, DFFc);
    dim3 gF2(2, cdiv(Nn, 128));
    gemm_pk<0><<<gF2, 256, GEMM_SMEM_PK>>>(Fpk, Wpk + OW2, nullptr, ff2, Nn, 3072, DIMc);
    k_zero_stats<<<1, 256>>>();
    k_bnstats<<<256, 256>>>(ff2);
    k_bnapply<false><<<cdiv(Nn * DIMc, 256), 256>>>(ff2, n3_g, n3_b, h2, out);
}

// round 8
// speedup vs baseline: 2.0794x; 1.1066x over previous
#include <cuda_runtime.h>
#include <cuda_bf16.h>
#include <cuda_fp16.h>
#include <math.h>
#include <stdint.h>

#define Nn    20000
#define Ee    320000
#define DIMc  256
#define Hh    8
#define EDIMc 32
#define DFFc  1024
#define ETOT  (Ee + Nn)

// ---------------- scratch (device globals) -----------------------------------
static __device__ float    g_xlr[(size_t)Nn * 512];
static __device__ __half   g_xlrh[(size_t)Nn * 512];
static __device__ float    g_loop[(size_t)Nn * EDIMc];
static __device__ float    g_cnt[Nn];
static __device__ float    g_sc [(size_t)ETOT * Hh];
static __device__ float    g_agg[(size_t)Nn * DIMc];
static __device__ float    g_h1 [(size_t)Nn * DIMc];
static __device__ float    g_h2 [(size_t)Nn * DIMc];
static __device__ float    g_ff2[(size_t)Nn * DIMc];
static __device__ float    g_sum[DIMc];
static __device__ float    g_sumsq[DIMc];
static __device__ int      g_rowptr[Nn + 1];
static __device__ int      g_tmp[Nn];
static __device__ int2     g_adj[Ee];

static __device__ __nv_bfloat16 g_Apk[(size_t)Nn * 768];
static __device__ __nv_bfloat16 g_Fpk[(size_t)Nn * 3072];
static __device__ __nv_bfloat16 g_EApk[(size_t)ETOT * 128];
#define OWLR1 0
#define OWE1  393216
#define OWLR2 425984
#define OWE2  819200
#define OW1   851968
#define OW2   1638400
#define WPK_TOTAL 2424832
static __device__ __nv_bfloat16 g_Wpk[WPK_TOTAL];

// ---------------- PTX helpers --------------------------------------------------
__device__ __forceinline__ uint32_t smem_u32(const void* p) {
    uint32_t a;
    asm("{ .reg .u64 t; cvta.to.shared.u64 t, %1; cvt.u32.u64 %0, t; }"
        : "=r"(a) : "l"(p));
    return a;
}
#define LDSM_X4(r0, r1, r2, r3, addr) \
    asm volatile("ldmatrix.sync.aligned.m8n8.x4.shared.b16 {%0,%1,%2,%3}, [%4];" \
                 : "=r"(r0), "=r"(r1), "=r"(r2), "=r"(r3) : "r"(addr))
#define LDSM_X2(r0, r1, addr) \
    asm volatile("ldmatrix.sync.aligned.m8n8.x2.shared.b16 {%0,%1}, [%2];" \
                 : "=r"(r0), "=r"(r1) : "r"(addr))
#define MMA16816(c, a0, a1, a2, a3, b0, b1) \
    asm volatile("mma.sync.aligned.m16n8k16.row.col.f32.bf16.bf16.f32 " \
                 "{%0,%1,%2,%3}, {%4,%5,%6,%7}, {%8,%9}, {%0,%1,%2,%3};" \
                 : "+f"((c)[0]), "+f"((c)[1]), "+f"((c)[2]), "+f"((c)[3]) \
                 : "r"(a0), "r"(a1), "r"(a2), "r"(a3), "r"(b0), "r"(b1))
__device__ __forceinline__ void cp_cg(uint32_t dst, const void* src, int sz) {
    asm volatile("cp.async.cg.shared.global [%0], [%1], 16, %2;"
                 :: "r"(dst), "l"(src), "r"(sz));
}
#define CP_COMMIT() asm volatile("cp.async.commit_group;" ::: "memory")
#define SMEM_SWZ(b) ((b) ^ (((b) >> 3) & 0x70))

// ---------------- pack kernels --------------------------------------------------
__global__ void k_pack_node(const float* __restrict__ X, __nv_bfloat16* __restrict__ A,
                            int rows, int K) {
    int i = blockIdx.x * blockDim.x + threadIdx.x;
    if (i >= rows * K) return;
    int r = i / K, k = i - r * K;
    float v = X[i];
    __nv_bfloat16 h = __float2bfloat16(v);
    __nv_bfloat16 l = __float2bfloat16(v - __bfloat162float(h));
    size_t b = (size_t)r * (3 * K);
    A[b + k] = h;
    A[b + K + k] = l;
    A[b + 2 * K + k] = h;
}
__global__ void k_pack_ea(const float* __restrict__ ew) {
    int i = blockIdx.x * blockDim.x + threadIdx.x;
    if (i >= ETOT * EDIMc) return;
    int r = i >> 5, k = i & 31;
    float v = (r < Ee) ? ew[i] : g_loop[(size_t)(r - Ee) * EDIMc + k];
    __nv_bfloat16 h = __float2bfloat16(v);
    __nv_bfloat16 l = __float2bfloat16(v - __bfloat162float(h));
    size_t b = (size_t)r * 128;
    g_EApk[b + k]      = h;
    g_EApk[b + 32 + k] = l;
    g_EApk[b + 64 + k] = h;
    g_EApk[b + 96 + k] = __float2bfloat16(0.f);
}
// all 8 weight packs in ONE launch
__device__ __forceinline__ void pack_w_one(const float* __restrict__ W,
                                           __nv_bfloat16* __restrict__ WT,
                                           int i, int K, int N, int Kp) {
    int k = i / N, n = i - k * N;
    float v = W[i];
    __nv_bfloat16 h = __float2bfloat16(v);
    __nv_bfloat16 l = __float2bfloat16(v - __bfloat162float(h));
    size_t b = (size_t)n * Kp;
    WT[b + k]         = h;
    WT[b + K + k]     = h;
    WT[b + 2 * K + k] = l;
    if (k < Kp - 3 * K) WT[b + 3 * K + k] = __float2bfloat16(0.f);
}
__global__ void k_packT_all(const float* w0, const float* w1, const float* w2,
                            const float* w3, const float* w4, const float* w5,
                            const float* w6, const float* w7,
                            __nv_bfloat16* __restrict__ WT) {
    int i = blockIdx.x * blockDim.x + threadIdx.x;
    // seg sizes: 65536,65536,8192,65536,65536,8192,262144,262144 -> total 802816
    if (i < 65536)        pack_w_one(w0, WT + OWLR1,               i,           DIMc, DIMc, 768);
    else if (i < 131072)  pack_w_one(w1, WT + OWLR1 + 196608,      i - 65536,   DIMc, DIMc, 768);
    else if (i < 139264)  pack_w_one(w2, WT + OWE1,                i - 131072,  EDIMc, DIMc, 128);
    else if (i < 204800)  pack_w_one(w3, WT + OWLR2,               i - 139264,  DIMc, DIMc, 768);
    else if (i < 270336)  pack_w_one(w4, WT + OWLR2 + 196608,      i - 204800,  DIMc, DIMc, 768);
    else if (i < 278528)  pack_w_one(w5, WT + OWE2,                i - 270336,  EDIMc, DIMc, 128);
    else if (i < 540672)  pack_w_one(w6, WT + OW1,                 i - 278528,  DIMc, DFFc, 768);
    else if (i < 802816)  pack_w_one(w7, WT + OW2,                 i - 540672,  DFFc, DIMc, 3072);
}

// ---------------- 3-stage pipelined bf16 GEMM (K-packed x3) --------------------
// EPI: 0 = fp32 out; 1 = relu+bias -> [hi|lo|hi] pack in g_Fpk; 2 = fp32 + fp16 shadow
#define GEMM_SMEM_PK 98304

template<int EPI>
__global__ void __launch_bounds__(256, 2) gemm_pk(
    const __nv_bfloat16* __restrict__ A, const __nv_bfloat16* __restrict__ BT,
    const float* __restrict__ bias, float* __restrict__ C,
    int M, int Kp, int Nc) {
    extern __shared__ __nv_bfloat16 sm[];
    uint32_t sb = smem_u32(sm);
    int tid  = threadIdx.x;
    int lane = tid & 31;
    int w    = tid >> 5;
    int wr   = w & 1;
    int wc   = w >> 1;
    int row0 = blockIdx.y * 128;
    int col0 = blockIdx.x * 128;

    float acc[4][4][4];
#pragma unroll
    for (int i = 0; i < 4; i++)
#pragma unroll
        for (int j = 0; j < 4; j++)
#pragma unroll
            for (int q = 0; q < 4; q++) acc[i][j][q] = 0.f;

    const int nch = Kp >> 6;

    auto issue = [&](int c) {
        if (c < nch) {
            int stage = c % 3;
            uint32_t sA = sb + (uint32_t)stage * 32768u;
            uint32_t sB = sA + 16384u;
            int k0 = c << 6;
#pragma unroll
            for (int p = 0; p < 4; p++) {
                int idx = tid + (p << 8);
                int row = idx >> 3, u = idx & 7;
                uint32_t soff = SMEM_SWZ((uint32_t)(row * 128 + u * 16));
                int gr = row0 + row;
                cp_cg(sA + soff, A + (size_t)gr * Kp + k0 + u * 8, gr < M ? 16 : 0);
                cp_cg(sB + soff, BT + (size_t)(col0 + row) * Kp + k0 + u * 8, 16);
            }
        }
        CP_COMMIT();
    };
    auto compute = [&](int c) {
        int stage = c % 3;
        uint32_t bA = sb + (uint32_t)stage * 32768u;
        uint32_t bB = bA + 16384u;
#pragma unroll
        for (int ks = 0; ks < 4; ks++) {
            uint32_t a[4][4], b[4][2];
#pragma unroll
            for (int mi = 0; mi < 4; mi++) {
                uint32_t byte = (uint32_t)((wr * 64 + mi * 16 + (lane & 15)) * 128 +
                                           ks * 32 + ((lane >> 4) << 4));
                LDSM_X4(a[mi][0], a[mi][1], a[mi][2], a[mi][3], bA + SMEM_SWZ(byte));
            }
#pragma unroll
            for (int ni = 0; ni < 4; ni++) {
                uint32_t byte = (uint32_t)((wc * 32 + ni * 8 + (lane & 7)) * 128 +
                                           ks * 32 + (((lane >> 3) & 1) << 4));
                LDSM_X2(b[ni][0], b[ni][1], bB + SMEM_SWZ(byte));
            }
#pragma unroll
            for (int mi = 0; mi < 4; mi++)
#pragma unroll
                for (int ni = 0; ni < 4; ni++)
                    MMA16816(acc[mi][ni], a[mi][0], a[mi][1], a[mi][2], a[mi][3],
                             b[ni][0], b[ni][1]);
        }
    };

    issue(0);
    issue(1);
    for (int c = 0; c < nch; c++) {
        asm volatile("cp.async.wait_group 1;" ::: "memory");
        __syncthreads();
        issue(c + 2);
        compute(c);
    }

#pragma unroll
    for (int mi = 0; mi < 4; mi++) {
#pragma unroll
        for (int ni = 0; ni < 4; ni++) {
            int r = row0 + wr * 64 + mi * 16 + (lane >> 2);
            int c = col0 + wc * 32 + ni * 8 + (lane & 3) * 2;
            float v0 = acc[mi][ni][0], v1 = acc[mi][ni][1];
            float v2 = acc[mi][ni][2], v3 = acc[mi][ni][3];
            if (EPI == 1) {
                float b0 = bias[c], b1 = bias[c + 1];
                v0 = fmaxf(v0 + b0, 0.f); v1 = fmaxf(v1 + b1, 0.f);
                v2 = fmaxf(v2 + b0, 0.f); v3 = fmaxf(v3 + b1, 0.f);
                __nv_bfloat16* P = g_Fpk;
#pragma unroll
                for (int hh = 0; hh < 2; hh++) {
                    int rr = r + hh * 8;
                    if (rr >= M) continue;
                    float u0 = hh ? v2 : v0, u1 = hh ? v3 : v1;
                    size_t base = (size_t)rr * 3072 + c;
                    __nv_bfloat162 hp = __floats2bfloat162_rn(u0, u1);
                    __nv_bfloat162 lp = __floats2bfloat162_rn(
                        u0 - __bfloat162float(hp.x), u1 - __bfloat162float(hp.y));
                    *(__nv_bfloat162*)&P[base]        = hp;
                    *(__nv_bfloat162*)&P[base + 1024] = lp;
                    *(__nv_bfloat162*)&P[base + 2048] = hp;
                }
            } else {
                if (r < M) {
                    C[(size_t)r * Nc + c] = v0;
                    C[(size_t)r * Nc + c + 1] = v1;
                    if (EPI == 2)
                        *(__half2*)(g_xlrh + (size_t)r * 512 + c) = __floats2half2_rn(v0, v1);
                }
                if (r + 8 < M) {
                    C[(size_t)(r + 8) * Nc + c] = v2;
                    C[(size_t)(r + 8) * Nc + c + 1] = v3;
                    if (EPI == 2)
                        *(__half2*)(g_xlrh + (size_t)(r + 8) * 512 + c) = __floats2half2_rn(v2, v3);
                }
            }
        }
    }
}

// ---------------- ee GEMM fused with GATv2 score (512 threads) ------------------
#define SC_SMEM 104448

__global__ void __launch_bounds__(512, 1) gemm_score(
    const __nv_bfloat16* __restrict__ A, const __nv_bfloat16* __restrict__ BT,
    const float* __restrict__ att,
    const int* __restrict__ src, const int* __restrict__ dst) {
    extern __shared__ char smc[];
    uint32_t sb = smem_u32(smc);
    float* sc_s  = (float*)(smc + 98304);
    float* att_s = (float*)(smc + 102400);
    int*   ss_s  = (int*)(smc + 103424);
    int*   sd_s  = (int*)(smc + 103936);
    int tid = threadIdx.x, lane = tid & 31, w = tid >> 5;
    int wr = w & 3, wc = w >> 2;          // 4 row-groups x 4 col-groups
    int row0 = blockIdx.x * 128;

    if (tid < 256) att_s[tid] = att[tid];
    if (tid < 128) {
        int e = row0 + tid;
        int s, d;
        if (e < Ee)       { s = src[e]; d = dst[e]; }
        else if (e < ETOT){ s = e - Ee; d = s; }
        else              { s = 0; d = 0; }
        ss_s[tid] = s; sd_s[tid] = d;
    }
#pragma unroll
    for (int p = 0; p < 4; p++) {
        int i = tid + (p << 9);
        int c = i >> 10, j = i & 1023;
        int row = j >> 3, u = j & 7;
        uint32_t soff = (uint32_t)c * 16384u + SMEM_SWZ((uint32_t)(row * 128 + u * 16));
        int gr = row0 + row;
        cp_cg(sb + soff, A + (size_t)gr * 128 + c * 64 + u * 8, gr < ETOT ? 16 : 0);
    }
#pragma unroll
    for (int p = 0; p < 8; p++) {
        int i = tid + (p << 9);
        int c = i >> 11, j = i & 2047;
        int row = j >> 3, u = j & 7;
        uint32_t soff = 32768u + (uint32_t)c * 32768u + SMEM_SWZ((uint32_t)(row * 128 + u * 16));
        cp_cg(sb + soff, BT + (size_t)row * 128 + c * 64 + u * 8, 16);
    }
    CP_COMMIT();
    asm volatile("cp.async.wait_group 0;" ::: "memory");
    __syncthreads();

    float acc[2][8][4];
#pragma unroll
    for (int i = 0; i < 2; i++)
#pragma unroll
        for (int j = 0; j < 8; j++)
#pragma unroll
            for (int q = 0; q < 4; q++) acc[i][j][q] = 0.f;

#pragma unroll
    for (int c = 0; c < 2; c++) {
        uint32_t bA = sb + (uint32_t)c * 16384u;
        uint32_t bB = sb + 32768u + (uint32_t)c * 32768u;
#pragma unroll
        for (int ks = 0; ks < 4; ks++) {
            uint32_t a[2][4], b[8][2];
#pragma unroll
            for (int mi = 0; mi < 2; mi++) {
                uint32_t byte = (uint32_t)((wr * 32 + mi * 16 + (lane & 15)) * 128 +
                                           ks * 32 + ((lane >> 4) << 4));
                LDSM_X4(a[mi][0], a[mi][1], a[mi][2], a[mi][3], bA + SMEM_SWZ(byte));
            }
#pragma unroll
            for (int ni = 0; ni < 8; ni++) {
                uint32_t byte = (uint32_t)((wc * 64 + ni * 8 + (lane & 7)) * 128 +
                                           ks * 32 + (((lane >> 3) & 1) << 4));
                LDSM_X2(b[ni][0], b[ni][1], bB + SMEM_SWZ(byte));
            }
#pragma unroll
            for (int mi = 0; mi < 2; mi++)
#pragma unroll
                for (int ni = 0; ni < 8; ni++)
                    MMA16816(acc[mi][ni], a[mi][0], a[mi][1], a[mi][2], a[mi][3],
                             b[ni][0], b[ni][1]);
        }
    }

    // epilogue: score = sum_c att[c] * lrelu(ee + xl[s][c] + xr[d][c])  (fp16 gather)
#pragma unroll
    for (int mi = 0; mi < 2; mi++) {
#pragma unroll
        for (int hf = 0; hf < 2; hf++) {
            int r = wr * 32 + mi * 16 + (lane >> 2) + hf * 8;
            int s = ss_s[r], d = sd_s[r];
            const __half* xlp = g_xlrh + (size_t)s * 512;
            const __half* xrp = g_xlrh + (size_t)d * 512 + 256;
            float h0 = 0.f, h1 = 0.f;
#pragma unroll
            for (int ni = 0; ni < 8; ni++) {
                int c0 = wc * 64 + ni * 8 + (lane & 3) * 2;
                float2 xlv = __half22float2(*(const __half2*)(xlp + c0));
                float2 xrv = __half22float2(*(const __half2*)(xrp + c0));
                float z0 = acc[mi][ni][hf * 2 + 0] + xlv.x + xrv.x;
                float z1 = acc[mi][ni][hf * 2 + 1] + xlv.y + xrv.y;
                z0 = (z0 > 0.f) ? z0 : 0.2f * z0;
                z1 = (z1 > 0.f) ? z1 : 0.2f * z1;
                float pp = z0 * att_s[c0] + z1 * att_s[c0 + 1];
                if (ni < 4) h0 += pp; else h1 += pp;
            }
            h0 += __shfl_xor_sync(0xffffffffu, h0, 1);
            h0 += __shfl_xor_sync(0xffffffffu, h0, 2);
            h1 += __shfl_xor_sync(0xffffffffu, h1, 1);
            h1 += __shfl_xor_sync(0xffffffffu, h1, 2);
            if ((lane & 3) == 0) {
                sc_s[r * 8 + wc * 2]     = h0;
                sc_s[r * 8 + wc * 2 + 1] = h1;
            }
        }
    }
    __syncthreads();
#pragma unroll
    for (int p = 0; p < 2; p++) {
        int i = tid + (p << 9);
        int r = i >> 3;
        int e = row0 + r;
        if (e < ETOT) g_sc[(size_t)e * 8 + (i & 7)] = sc_s[i];
    }
}

// ---------------- self-loop mean + CSR build ------------------------------------
__global__ void k_zero_loop() {
    int i = blockIdx.x * blockDim.x + threadIdx.x;
    if (i < Nn * EDIMc) g_loop[i] = 0.f;
    if (i < Nn)         g_cnt[i]  = 0.f;
}
__global__ void k_loop_accum(const int* __restrict__ dst, const float* __restrict__ ew) {
    int w    = (blockIdx.x * blockDim.x + threadIdx.x) >> 5;
    int lane = threadIdx.x & 31;
    if (w >= Ee) return;
    int d = dst[w];
    atomicAdd(&g_loop[d * EDIMc + lane], ew[(size_t)w * EDIMc + lane]);
    if (lane == 0) atomicAdd(&g_cnt[d], 1.f);
}
__global__ void k_loop_div() {
    int i = blockIdx.x * blockDim.x + threadIdx.x;
    if (i >= Nn * EDIMc) return;
    g_loop[i] /= fmaxf(g_cnt[i >> 5], 1.f);
}
__global__ void k_scan() {
    __shared__ int part[1024];
    int t = threadIdx.x;
    const int SEG = (Nn + 1023) / 1024;
    int base = t * SEG;
    int s = 0;
    for (int i = 0; i < SEG; i++) {
        int idx = base + i;
        if (idx < Nn) s += (int)g_cnt[idx];
    }
    part[t] = s;
    __syncthreads();
    for (int off = 1; off < 1024; off <<= 1) {
        int v = (t >= off) ? part[t - off] : 0;
        __syncthreads();
        part[t] += v;
        __syncthreads();
    }
    int run = (t == 0) ? 0 : part[t - 1];
    for (int i = 0; i < SEG; i++) {
        int idx = base + i;
        if (idx < Nn) {
            g_rowptr[idx] = run;
            g_tmp[idx] = run;
            run += (int)g_cnt[idx];
        }
    }
    if (t == 1023) g_rowptr[Nn] = run;
}
__global__ void k_scatter(const int* __restrict__ src, const int* __restrict__ dst) {
    int e = blockIdx.x * blockDim.x + threadIdx.x;
    if (e >= Ee) return;
    int pos = atomicAdd(&g_tmp[dst[e]], 1);
    g_adj[pos] = make_int2(src[e], e);
}

// ---------------- per-node fused softmax + aggregation (2-pass) ------------------
__global__ void k_node() {
    int d    = blockIdx.x * 8 + (threadIdx.x >> 5);
    int lane = threadIdx.x & 31;
    if (d >= Nn) return;
    int beg = g_rowptr[d], end = g_rowptr[d + 1];
    const float* ssc = g_sc + (size_t)(Ee + d) * Hh;

    float mx[Hh];
#pragma unroll
    for (int h = 0; h < Hh; h++) mx[h] = ssc[h];
    for (int i = beg + lane; i < end; i += 32) {
        const float* sc = g_sc + (size_t)g_adj[i].y * Hh;
#pragma unroll
        for (int h = 0; h < Hh; h++) mx[h] = fmaxf(mx[h], sc[h]);
    }
#pragma unroll
    for (int off = 16; off; off >>= 1)
#pragma unroll
        for (int h = 0; h < Hh; h++)
            mx[h] = fmaxf(mx[h], __shfl_xor_sync(0xffffffffu, mx[h], off));

    int hh = lane >> 2;
    int c0 = lane << 3;
    float m_h = mx[hh];

    float den;
    float acc[8];
    {
        float a = __expf(ssc[hh] - m_h);
        den = a;
        const float4* xp = (const float4*)(g_xlr + (size_t)d * 512 + c0);
        float4 u0 = xp[0], u1 = xp[1];
        acc[0] = a * u0.x; acc[1] = a * u0.y; acc[2] = a * u0.z; acc[3] = a * u0.w;
        acc[4] = a * u1.x; acc[5] = a * u1.y; acc[6] = a * u1.z; acc[7] = a * u1.w;
    }
    for (int i = beg; i < end; i++) {
        int2 se = g_adj[i];
        float a = __expf(g_sc[(size_t)se.y * Hh + hh] - m_h);
        den += a;
        const float4* xp = (const float4*)(g_xlr + (size_t)se.x * 512 + c0);
        float4 u0 = xp[0], u1 = xp[1];
        acc[0] += a * u0.x; acc[1] += a * u0.y; acc[2] += a * u0.z; acc[3] += a * u0.w;
        acc[4] += a * u1.x; acc[5] += a * u1.y; acc[6] += a * u1.z; acc[7] += a * u1.w;
    }
    float inv = 1.f / den;
#pragma unroll
    for (int q = 0; q < 8; q++) acc[q] *= inv;

    float4* op = (float4*)(g_agg + (size_t)d * DIMc + c0);
    op[0] = make_float4(acc[0], acc[1], acc[2], acc[3]);
    op[1] = make_float4(acc[4], acc[5], acc[6], acc[7]);
}

// ---------------- BatchNorm -------------------------------------------------------
__global__ void k_zero_stats() {
    int t = threadIdx.x;
    if (t < DIMc) { g_sum[t] = 0.f; g_sumsq[t] = 0.f; }
}
__global__ void k_bnstats(const float* __restrict__ X) {
    int c = threadIdx.x;
    float s = 0.f, q = 0.f;
    for (int r = blockIdx.x; r < Nn; r += gridDim.x) {
        float v = X[(size_t)r * DIMc + c];
        s += v; q += v * v;
    }
    atomicAdd(&g_sum[c], s);
    atomicAdd(&g_sumsq[c], q);
}
template<bool PACK>
__global__ void k_bnapply(const float* __restrict__ X, const float* __restrict__ gam,
                          const float* __restrict__ bet, const float* __restrict__ res,
                          float* __restrict__ out) {
    int i = blockIdx.x * blockDim.x + threadIdx.x;
    if (i >= Nn * DIMc) return;
    int c = i & (DIMc - 1);
    float mu  = g_sum[c]   * (1.f / Nn);
    float var = g_sumsq[c] * (1.f / Nn) - mu * mu;
    float y = (X[i] - mu) * rsqrtf(var + 1e-5f) * gam[c] + bet[c];
    y = (y > 0.f) ? y : 0.01f * y;
    float v = res[i] + y;
    out[i] = v;
    if (PACK) {
        int r = i >> 8;
        __nv_bfloat16 h = __float2bfloat16(v);
        size_t b = (size_t)r * 768 + c;
        g_Apk[b]       = h;
        g_Apk[b + 256] = __float2bfloat16(v - __bfloat162float(h));
        g_Apk[b + 512] = h;
    }
}

// ---------------- host orchestration ----------------------------------------------
static inline int cdiv(int a, int b) { return (a + b - 1) / b; }

extern "C" void kernel_launch(void* const* d_in, const int* in_sizes, int n_in,
                              void* d_out, int out_size) {
    const float* nf    = (const float*)d_in[0];
    const int*   ei    = (const int*)  d_in[1];
    const float* ew    = (const float*)d_in[2];
    const float* g1_Wl = (const float*)d_in[3];
    const float* g1_Wr = (const float*)d_in[4];
    const float* g1_We = (const float*)d_in[5];
    const float* g1_at = (const float*)d_in[6];
    const float* g2_Wl = (const float*)d_in[8];
    const float* g2_Wr = (const float*)d_in[9];
    const float* g2_We = (const float*)d_in[10];
    const float* g2_at = (const float*)d_in[11];
    const float* n1_g  = (const float*)d_in[13];
    const float* n1_b  = (const float*)d_in[14];
    const float* n2_g  = (const float*)d_in[15];
    const float* n2_b  = (const float*)d_in[16];
    const float* n3_g  = (const float*)d_in[17];
    const float* n3_b  = (const float*)d_in[18];
    const float* ff_W1 = (const float*)d_in[19];
    const float* ff_b1 = (const float*)d_in[20];
    const float* ff_W2 = (const float*)d_in[21];
    const int* src = ei;
    const int* dst = ei + Ee;
    float* out = (float*)d_out;

    void* p;
    cudaGetSymbolAddress(&p, g_xlr);  float* xlr  = (float*)p;
    cudaGetSymbolAddress(&p, g_agg);  float* agg  = (float*)p;
    cudaGetSymbolAddress(&p, g_h1);   float* h1   = (float*)p;
    cudaGetSymbolAddress(&p, g_h2);   float* h2   = (float*)p;
    cudaGetSymbolAddress(&p, g_ff2);  float* ff2  = (float*)p;
    cudaGetSymbolAddress(&p, g_Apk);  __nv_bfloat16* Apk = (__nv_bfloat16*)p;
    cudaGetSymbolAddress(&p, g_Fpk);  __nv_bfloat16* Fpk = (__nv_bfloat16*)p;
    cudaGetSymbolAddress(&p, g_EApk); __nv_bfloat16* EApk = (__nv_bfloat16*)p;
    cudaGetSymbolAddress(&p, g_Wpk);  __nv_bfloat16* Wpk = (__nv_bfloat16*)p;

    cudaFuncSetAttribute(gemm_pk<0>, cudaFuncAttributeMaxDynamicSharedMemorySize, GEMM_SMEM_PK);
    cudaFuncSetAttribute(gemm_pk<1>, cudaFuncAttributeMaxDynamicSharedMemorySize, GEMM_SMEM_PK);
    cudaFuncSetAttribute(gemm_pk<2>, cudaFuncAttributeMaxDynamicSharedMemorySize, GEMM_SMEM_PK);
    cudaFuncSetAttribute(gemm_score, cudaFuncAttributeMaxDynamicSharedMemorySize, SC_SMEM);

    // ---- all weight packs in one launch ----
    k_packT_all<<<cdiv(802816, 256), 256>>>(g1_Wl, g1_Wr, g1_We, g2_Wl, g2_Wr, g2_We,
                                            ff_W1, ff_W2, Wpk);

    // ---- self-loop edge features + CSR (once) ----
    k_zero_loop<<<cdiv(Nn * EDIMc, 256), 256>>>();
    k_loop_accum<<<cdiv(Ee * 32, 256), 256>>>(dst, ew);
    k_loop_div<<<cdiv(Nn * EDIMc, 256), 256>>>();
    k_scan<<<1, 1024>>>();
    k_scatter<<<cdiv(Ee, 256), 256>>>(src, dst);
    k_pack_ea<<<cdiv(ETOT * EDIMc, 256), 256>>>(ew);

    dim3 gXLR(4, cdiv(Nn, 128));
    int nbScore = cdiv(ETOT, 128);
    int nbNode  = cdiv(Nn, 8);

    // ---- block 1 ----
    k_pack_node<<<cdiv(Nn * DIMc, 256), 256>>>(nf, Apk, Nn, DIMc);
    gemm_pk<2><<<gXLR, 256, GEMM_SMEM_PK>>>(Apk, Wpk + OWLR1, nullptr, xlr, Nn, 768, 512);
    gemm_score<<<nbScore, 512, SC_SMEM>>>(EApk, Wpk + OWE1, g1_at, src, dst);
    k_node<<<nbNode, 256>>>();
    k_zero_stats<<<1, 256>>>();
    k_bnstats<<<256, 256>>>(agg);
    k_bnapply<true><<<cdiv(Nn * DIMc, 256), 256>>>(agg, n1_g, n1_b, nf, h1);

    // ---- block 2 ----
    gemm_pk<2><<<gXLR, 256, GEMM_SMEM_PK>>>(Apk, Wpk + OWLR2, nullptr, xlr, Nn, 768, 512);
    gemm_score<<<nbScore, 512, SC_SMEM>>>(EApk, Wpk + OWE2, g2_at, src, dst);
    k_node<<<nbNode, 256>>>();
    k_zero_stats<<<1, 256>>>();
    k_bnstats<<<256, 256>>>(agg);
    k_bnapply<true><<<cdiv(Nn * DIMc, 256), 256>>>(agg, n2_g, n2_b, h1, h2);

    // ---- feed-forward ----
    dim3 gF1(8, cdiv(Nn, 128));
    gemm_pk<1><<<gF1, 256, GEMM_SMEM_PK>>>(Apk, Wpk + OW1, ff_b1, nullptr, Nn, 768, DFFc);
    dim3 gF2(2, cdiv(Nn, 128));
    gemm_pk<0><<<gF2, 256, GEMM_SMEM_PK>>>(Fpk, Wpk + OW2, nullptr, ff2, Nn, 3072, DIMc);
    k_zero_stats<<<1, 256>>>();
    k_bnstats<<<256, 256>>>(ff2);
    k_bnapply<false><<<cdiv(Nn * DIMc, 256), 256>>>(ff2, n3_g, n3_b, h2, out);
}